// round 9
// baseline (speedup 1.0000x reference)
#include <cuda_runtime.h>
#include <cuda_bf16.h>
#include <cstdint>

// Problem dims
#define Bb   64
#define Tt   256
#define Cc   384
#define Hh   6
#define HSZ  64
#define MM   (Bb*Tt)     // 16384 tokens
#define NQKV (3*Cc)      // 1152
#define FF   (4*Cc)      // 1536

// ================= helpers =================
__device__ __forceinline__ uint32_t smem_u32(const void* p) {
    uint32_t a;
    asm("{ .reg .u64 t; cvta.to.shared.u64 t, %1; cvt.u32.u64 %0, t; }" : "=r"(a) : "l"(p));
    return a;
}
#define SMEM_SWIZZLE_128B(off) ((off) ^ (((off) >> 3) & 0x70))

#define CP_ASYNC16(dst, src) \
    asm volatile("cp.async.cg.shared.global [%0], [%1], 16;" :: "r"(dst), "l"(src))
#define CP_COMMIT() asm volatile("cp.async.commit_group;" ::: "memory")
#define CP_WAIT(n)  asm volatile("cp.async.wait_group %0;" :: "n"(n) : "memory")

#define LDSM_X4(r0, r1, r2, r3, addr) \
    asm volatile("ldmatrix.sync.aligned.m8n8.x4.shared.b16 {%0,%1,%2,%3}, [%4];" \
        : "=r"(r0), "=r"(r1), "=r"(r2), "=r"(r3) : "r"(addr))

#define MMA16816(d, a, b) \
    asm volatile("mma.sync.aligned.m16n8k16.row.col.f32.bf16.bf16.f32 " \
        "{%0,%1,%2,%3}, {%4,%5,%6,%7}, {%8,%9}, {%0,%1,%2,%3};" \
        : "+f"((d)[0]), "+f"((d)[1]), "+f"((d)[2]), "+f"((d)[3]) \
        : "r"((a)[0]), "r"((a)[1]), "r"((a)[2]), "r"((a)[3]), "r"((b)[0]), "r"((b)[1]))

// ================= scratch (device globals) =================
__device__ __align__(16) __nv_bfloat16 g_h_hi [MM*Cc];
__device__ __align__(16) __nv_bfloat16 g_h_lo [MM*Cc];
__device__ __align__(16) float         g_qkv  [MM*NQKV];
__device__ __align__(16) __nv_bfloat16 g_o_hi [MM*Cc];
__device__ __align__(16) __nv_bfloat16 g_o_lo [MM*Cc];
__device__ __align__(16) float         g_x1   [MM*Cc];
__device__ __align__(16) __nv_bfloat16 g_h2_hi[MM*Cc];
__device__ __align__(16) __nv_bfloat16 g_h2_lo[MM*Cc];
__device__ __align__(16) __nv_bfloat16 g_ff_hi[MM*FF];
__device__ __align__(16) __nv_bfloat16 g_ff_lo[MM*FF];
// packed/transposed weights [N][K] bf16 hi/lo
__device__ __align__(16) __nv_bfloat16 g_wqkvT_hi[NQKV*Cc];
__device__ __align__(16) __nv_bfloat16 g_wqkvT_lo[NQKV*Cc];
__device__ __align__(16) __nv_bfloat16 g_wpT_hi[Cc*Cc];
__device__ __align__(16) __nv_bfloat16 g_wpT_lo[Cc*Cc];
__device__ __align__(16) __nv_bfloat16 g_w1T_hi[FF*Cc];
__device__ __align__(16) __nv_bfloat16 g_w1T_lo[FF*Cc];
__device__ __align__(16) __nv_bfloat16 g_w2T_hi[Cc*FF];
__device__ __align__(16) __nv_bfloat16 g_w2T_lo[Cc*FF];

__device__ __forceinline__ void split2(float x, __nv_bfloat16& hi, __nv_bfloat16& lo) {
    hi = __float2bfloat16(x);
    lo = __float2bfloat16(x - __bfloat162float(hi));
}

// ================= weight pack kernels =================
__global__ void pack_qkvT_kernel(const float* __restrict__ Wq,
                                 const float* __restrict__ Wk,
                                 const float* __restrict__ Wv) {
    int idx = blockIdx.x * 256 + threadIdx.x;
    if (idx >= NQKV * Cc) return;
    int n = idx / Cc, k = idx % Cc;
    int which = n / Cc;
    int hd    = n % Cc;
    int h = hd / HSZ, d = hd % HSZ;
    const float* W = (which == 0) ? Wq : (which == 1) ? Wk : Wv;
    split2(W[(h * Cc + k) * HSZ + d], g_wqkvT_hi[idx], g_wqkvT_lo[idx]);
}

// generic transpose+split: out[n][k] = W[k*N + n]   (W is [K][N])
__global__ void convT_kernel(const float* __restrict__ W,
                             __nv_bfloat16* __restrict__ hi,
                             __nv_bfloat16* __restrict__ lo, int K, int N) {
    int idx = blockIdx.x * 256 + threadIdx.x;
    if (idx >= N * K) return;
    int n = idx / K, k = idx % K;
    split2(W[(size_t)k * N + n], hi[idx], lo[idx]);
}

// ================= LayerNorm -> bf16 hi/lo =================
__global__ void ln_kernel(const float* __restrict__ x,
                          const float* __restrict__ gamma,
                          const float* __restrict__ beta,
                          __nv_bfloat16* __restrict__ yhi,
                          __nv_bfloat16* __restrict__ ylo) {
    int row = blockIdx.x;
    const float* xr = x + (size_t)row * Cc;
    int tid = threadIdx.x;  // 128 threads, 3 elems each
    float v0 = xr[tid], v1 = xr[tid + 128], v2 = xr[tid + 256];
    float s  = v0 + v1 + v2;
    float sq = v0 * v0 + v1 * v1 + v2 * v2;
    #pragma unroll
    for (int o = 16; o > 0; o >>= 1) {
        s  += __shfl_down_sync(0xffffffffu, s,  o);
        sq += __shfl_down_sync(0xffffffffu, sq, o);
    }
    __shared__ float ss[4], sqs[4];
    int wid = tid >> 5, lid = tid & 31;
    if (lid == 0) { ss[wid] = s; sqs[wid] = sq; }
    __syncthreads();
    if (tid == 0) {
        float S  = ss[0] + ss[1] + ss[2] + ss[3];
        float SQ = sqs[0] + sqs[1] + sqs[2] + sqs[3];
        float mu  = S / (float)Cc;
        float var = SQ / (float)Cc - mu * mu;
        ss[0]  = mu;
        sqs[0] = rsqrtf(var + 1e-3f);
    }
    __syncthreads();
    float mu = ss[0], inv = sqs[0];
    size_t base = (size_t)row * Cc;
    float y0 = (v0 - mu) * inv * gamma[tid]       + beta[tid];
    float y1 = (v1 - mu) * inv * gamma[tid + 128] + beta[tid + 128];
    float y2 = (v2 - mu) * inv * gamma[tid + 256] + beta[tid + 256];
    split2(y0, yhi[base + tid],       ylo[base + tid]);
    split2(y1, yhi[base + tid + 128], ylo[base + tid + 128]);
    split2(y2, yhi[base + tid + 256], ylo[base + tid + 256]);
}

// ================= mma.sync split-bf16 GEMM =================
// C[M,N] = A[M,K] * B^T  with A=[M][K] hi/lo bf16, B=[N][K] hi/lo bf16.
// CTA tile 128x128, BK=64, cp.async double buffer.
// 512 threads / 16 warps, each warp a 32x32 tile (4x4 warp grid) for
// higher warp count per SM (latency hiding; acc budget fixed per CTA).
#define GEMM_DSMEM (1024 + 2 * 65536)

__device__ __forceinline__ void load_tile_async(const __nv_bfloat16* __restrict__ src,
                                                int row0, int k0, int Ktot,
                                                uint32_t dstbase, int tid) {
    #pragma unroll
    for (int j = 0; j < 2; j++) {
        int idx = tid + j * 512;         // 1024 x 16B = 128 rows x 128B
        int r = idx >> 3, c16 = idx & 7;
        const __nv_bfloat16* g = src + (size_t)(row0 + r) * Ktot + k0 + c16 * 8;
        uint32_t s = dstbase + SMEM_SWIZZLE_128B((uint32_t)(r * 128 + c16 * 16));
        CP_ASYNC16(s, g);
    }
}

template<int BIAS, int RES, int RELU, int F32OUT, int BFOUT>
__global__ __launch_bounds__(512)
void mma_gemm_kernel(const __nv_bfloat16* __restrict__ Ahi, const __nv_bfloat16* __restrict__ Alo,
                     const __nv_bfloat16* __restrict__ Bhi, const __nv_bfloat16* __restrict__ Blo,
                     const float* __restrict__ bias, const float* __restrict__ res,
                     float* __restrict__ Cf,
                     __nv_bfloat16* __restrict__ Chi, __nv_bfloat16* __restrict__ Clo,
                     int M, int N, int K) {
    extern __shared__ char dsm[];
    uint32_t raw  = smem_u32(dsm);
    uint32_t base = (raw + 1023) & ~1023u;

    int tid = threadIdx.x, wid = tid >> 5, lane = tid & 31;
    int warp_m = (wid >> 2) * 32;   // 0,32,64,96
    int warp_n = (wid & 3) * 32;    // 0,32,64,96
    int m0 = blockIdx.y * 128, n0 = blockIdx.x * 128;
    int nch = K >> 6;

    float acc[2][4][4];
    #pragma unroll
    for (int a = 0; a < 2; a++)
        #pragma unroll
        for (int b = 0; b < 4; b++)
            #pragma unroll
            for (int c = 0; c < 4; c++) acc[a][b][c] = 0.f;

    // prologue: chunk 0 -> buffer 0
    load_tile_async(Ahi, m0, 0, K, base + 0,     tid);
    load_tile_async(Alo, m0, 0, K, base + 16384, tid);
    load_tile_async(Bhi, n0, 0, K, base + 32768, tid);
    load_tile_async(Blo, n0, 0, K, base + 49152, tid);
    CP_COMMIT();

    // ldmatrix lane mapping
    int q = lane >> 3, rin = lane & 7;
    int a_row_off = (q & 1) * 8 + rin;       // + mf*16
    int a_col_off = (q >> 1) * 8;            // + ks*16
    int b_row_off = (q >> 1) * 8 + rin;      // + nf2*16
    int b_col_off = (q & 1) * 8;             // + ks*16

    for (int i = 0; i < nch; i++) {
        if (i + 1 < nch) {
            uint32_t nb = base + ((i + 1) & 1) * 65536;
            int k0 = (i + 1) << 6;
            load_tile_async(Ahi, m0, k0, K, nb + 0,     tid);
            load_tile_async(Alo, m0, k0, K, nb + 16384, tid);
            load_tile_async(Bhi, n0, k0, K, nb + 32768, tid);
            load_tile_async(Blo, n0, k0, K, nb + 49152, tid);
            CP_COMMIT();
            CP_WAIT(1);
        } else {
            CP_WAIT(0);
        }
        __syncthreads();

        uint32_t buf = base + (i & 1) * 65536;
        uint32_t sAhi = buf + 0, sAlo = buf + 16384;
        uint32_t sBhi = buf + 32768, sBlo = buf + 49152;

        #pragma unroll
        for (int ks = 0; ks < 4; ks++) {
            uint32_t ahi[2][4], alo[2][4], bhi[4][2], blo[4][2];
            #pragma unroll
            for (int mf = 0; mf < 2; mf++) {
                uint32_t off = (uint32_t)((warp_m + mf * 16 + a_row_off) * 128 +
                                          (ks * 16 + a_col_off) * 2);
                LDSM_X4(ahi[mf][0], ahi[mf][1], ahi[mf][2], ahi[mf][3],
                        sAhi + SMEM_SWIZZLE_128B(off));
                LDSM_X4(alo[mf][0], alo[mf][1], alo[mf][2], alo[mf][3],
                        sAlo + SMEM_SWIZZLE_128B(off));
            }
            #pragma unroll
            for (int nf2 = 0; nf2 < 2; nf2++) {
                uint32_t off = (uint32_t)((warp_n + nf2 * 16 + b_row_off) * 128 +
                                          (ks * 16 + b_col_off) * 2);
                LDSM_X4(bhi[nf2 * 2][0], bhi[nf2 * 2][1], bhi[nf2 * 2 + 1][0], bhi[nf2 * 2 + 1][1],
                        sBhi + SMEM_SWIZZLE_128B(off));
                LDSM_X4(blo[nf2 * 2][0], blo[nf2 * 2][1], blo[nf2 * 2 + 1][0], blo[nf2 * 2 + 1][1],
                        sBlo + SMEM_SWIZZLE_128B(off));
            }
            #pragma unroll
            for (int mf = 0; mf < 2; mf++)
                #pragma unroll
                for (int nf = 0; nf < 4; nf++) MMA16816(acc[mf][nf], ahi[mf], bhi[nf]);
            #pragma unroll
            for (int mf = 0; mf < 2; mf++)
                #pragma unroll
                for (int nf = 0; nf < 4; nf++) MMA16816(acc[mf][nf], alo[mf], bhi[nf]);
            #pragma unroll
            for (int mf = 0; mf < 2; mf++)
                #pragma unroll
                for (int nf = 0; nf < 4; nf++) MMA16816(acc[mf][nf], ahi[mf], blo[nf]);
        }
        __syncthreads();
    }

    // epilogue: direct register -> global with fused ops
    int tr = lane >> 2, tc = (lane & 3) * 2;
    #pragma unroll
    for (int mf = 0; mf < 2; mf++) {
        #pragma unroll
        for (int nf = 0; nf < 4; nf++) {
            int col = n0 + warp_n + nf * 8 + tc;
            #pragma unroll
            for (int half = 0; half < 2; half++) {
                int row = m0 + warp_m + mf * 16 + tr + half * 8;
                float v0 = acc[mf][nf][half * 2 + 0];
                float v1 = acc[mf][nf][half * 2 + 1];
                if (BIAS) { v0 += bias[col]; v1 += bias[col + 1]; }
                size_t oidx = (size_t)row * N + col;
                if (RES)  { v0 += res[oidx]; v1 += res[oidx + 1]; }
                if (RELU) { v0 = fmaxf(v0, 0.f); v1 = fmaxf(v1, 0.f); }
                if (F32OUT) {
                    Cf[oidx] = v0; Cf[oidx + 1] = v1;
                }
                if (BFOUT) {
                    split2(v0, Chi[oidx], Clo[oidx]);
                    split2(v1, Chi[oidx + 1], Clo[oidx + 1]);
                }
            }
        }
    }
}

// ================= causal attention (fp32, lane-pair split over head dim) ====
// 128 threads/block: thread t handles query (t>>1), head-dim half (t&1)*32.
// Partners are adjacent lanes -> shfl_xor(1) combines half-dots.
__global__ __launch_bounds__(128)
void attn_kernel(const float* __restrict__ qkv,
                 __nv_bfloat16* __restrict__ ohi, __nv_bfloat16* __restrict__ olo) {
    __shared__ float4 Kt[64][16];
    __shared__ float4 Vt[64][16];
    int b = blockIdx.z, h = blockIdx.y;
    int t = threadIdx.x;
    int qi = t >> 1, half = t & 1;
    int tq = blockIdx.x * 64 + qi;

    const float* qrow = qkv + ((size_t)(b * Tt + tq)) * NQKV + h * HSZ + half * 32;
    float4 q[8];
    #pragma unroll
    for (int i = 0; i < 8; i++) q[i] = *(const float4*)(qrow + 4 * i);

    float4 acc[8];
    #pragma unroll
    for (int i = 0; i < 8; i++) acc[i] = make_float4(0.f, 0.f, 0.f, 0.f);
    float m = -1e30f, l = 0.f;
    const float scale = 0.125f;

    for (int kt = 0; kt <= blockIdx.x; kt++) {
        // load K/V tile: thread loads row t>>1, 8 float4 at half*8
        {
            int lr = qi, lh = half;
            const float* kr = qkv + ((size_t)(b * Tt + kt * 64 + lr)) * NQKV + Cc + h * HSZ + lh * 32;
            const float* vr = kr + Cc;
            #pragma unroll
            for (int i = 0; i < 8; i++) {
                Kt[lr][lh * 8 + i] = *(const float4*)(kr + 4 * i);
                Vt[lr][lh * 8 + i] = *(const float4*)(vr + 4 * i);
            }
        }
        __syncthreads();

        bool diag = (kt == blockIdx.x);
        #pragma unroll 4
        for (int j = 0; j < 64; j++) {
            // half dot (uniform control flow; shuffle always executed)
            float sd = 0.f;
            #pragma unroll
            for (int i = 0; i < 8; i++) {
                float4 kk = Kt[j][half * 8 + i];
                sd += q[i].x * kk.x + q[i].y * kk.y + q[i].z * kk.z + q[i].w * kk.w;
            }
            sd += __shfl_xor_sync(0xffffffffu, sd, 1);
            sd *= scale;
            bool valid = !diag || (j <= qi);
            if (valid) {
                float p;
                if (sd > m) {
                    float corr = __expf(m - sd);
                    l *= corr;
                    #pragma unroll
                    for (int i = 0; i < 8; i++) {
                        acc[i].x *= corr; acc[i].y *= corr; acc[i].z *= corr; acc[i].w *= corr;
                    }
                    m = sd;
                    p = 1.f;
                } else {
                    p = __expf(sd - m);
                }
                l += p;
                #pragma unroll
                for (int i = 0; i < 8; i++) {
                    float4 vv = Vt[j][half * 8 + i];
                    acc[i].x += p * vv.x; acc[i].y += p * vv.y;
                    acc[i].z += p * vv.z; acc[i].w += p * vv.w;
                }
            }
            if (diag && j >= 63) break;
        }
        __syncthreads();
    }

    float inv = 1.f / l;
    size_t obase = ((size_t)(b * Tt + tq)) * Cc + h * HSZ + half * 32;
    #pragma unroll
    for (int i = 0; i < 8; i++) {
        float4 v = acc[i];
        split2(v.x * inv, ohi[obase + 4 * i + 0], olo[obase + 4 * i + 0]);
        split2(v.y * inv, ohi[obase + 4 * i + 1], olo[obase + 4 * i + 1]);
        split2(v.z * inv, ohi[obase + 4 * i + 2], olo[obase + 4 * i + 2]);
        split2(v.w * inv, ohi[obase + 4 * i + 3], olo[obase + 4 * i + 3]);
    }
}

// ================= host launch =================
template <typename T>
static T* sym_addr(const T* symbol) {
    void* p = nullptr;
    cudaGetSymbolAddress(&p, (const void*)symbol);
    return (T*)p;
}

extern "C" void kernel_launch(void* const* d_in, const int* in_sizes, int n_in,
                              void* d_out, int out_size) {
    const float* x   = (const float*)d_in[0];
    const float* Wq  = (const float*)d_in[1];
    const float* Wk  = (const float*)d_in[2];
    const float* Wv  = (const float*)d_in[3];
    const float* Wp  = (const float*)d_in[4];
    const float* bp  = (const float*)d_in[5];
    const float* W1  = (const float*)d_in[6];
    const float* b1  = (const float*)d_in[7];
    const float* W2  = (const float*)d_in[8];
    const float* b2  = (const float*)d_in[9];
    const float* g1  = (const float*)d_in[10];
    const float* be1 = (const float*)d_in[11];
    const float* g2  = (const float*)d_in[12];
    const float* be2 = (const float*)d_in[13];
    float* out = (float*)d_out;

    __nv_bfloat16* p_h_hi  = sym_addr(g_h_hi);
    __nv_bfloat16* p_h_lo  = sym_addr(g_h_lo);
    float*         p_qkv   = sym_addr(g_qkv);
    __nv_bfloat16* p_o_hi  = sym_addr(g_o_hi);
    __nv_bfloat16* p_o_lo  = sym_addr(g_o_lo);
    float*         p_x1    = sym_addr(g_x1);
    __nv_bfloat16* p_h2_hi = sym_addr(g_h2_hi);
    __nv_bfloat16* p_h2_lo = sym_addr(g_h2_lo);
    __nv_bfloat16* p_ff_hi = sym_addr(g_ff_hi);
    __nv_bfloat16* p_ff_lo = sym_addr(g_ff_lo);
    __nv_bfloat16* p_wqkvT_hi = sym_addr(g_wqkvT_hi);
    __nv_bfloat16* p_wqkvT_lo = sym_addr(g_wqkvT_lo);
    __nv_bfloat16* p_wpT_hi   = sym_addr(g_wpT_hi);
    __nv_bfloat16* p_wpT_lo   = sym_addr(g_wpT_lo);
    __nv_bfloat16* p_w1T_hi   = sym_addr(g_w1T_hi);
    __nv_bfloat16* p_w1T_lo   = sym_addr(g_w1T_lo);
    __nv_bfloat16* p_w2T_hi   = sym_addr(g_w2T_hi);
    __nv_bfloat16* p_w2T_lo   = sym_addr(g_w2T_lo);

    cudaFuncSetAttribute(mma_gemm_kernel<0,0,0,1,0>, cudaFuncAttributeMaxDynamicSharedMemorySize, GEMM_DSMEM);
    cudaFuncSetAttribute(mma_gemm_kernel<1,1,0,1,0>, cudaFuncAttributeMaxDynamicSharedMemorySize, GEMM_DSMEM);
    cudaFuncSetAttribute(mma_gemm_kernel<1,0,1,0,1>, cudaFuncAttributeMaxDynamicSharedMemorySize, GEMM_DSMEM);

    // 1. weight packing (transposed + bf16 split)
    pack_qkvT_kernel<<<(NQKV * Cc + 255) / 256, 256>>>(Wq, Wk, Wv);
    convT_kernel<<<(Cc * Cc + 255) / 256, 256>>>(Wp, p_wpT_hi, p_wpT_lo, Cc, Cc);
    convT_kernel<<<(Cc * FF + 255) / 256, 256>>>(W1, p_w1T_hi, p_w1T_lo, Cc, FF);
    convT_kernel<<<(FF * Cc + 255) / 256, 256>>>(W2, p_w2T_hi, p_w2T_lo, FF, Cc);

    // 2. LN1 -> bf16 split
    ln_kernel<<<MM, 128>>>(x, g1, be1, p_h_hi, p_h_lo);

    // 3. fused QKV projection: [16384,384] x [384,1152] -> fp32 qkv
    mma_gemm_kernel<0,0,0,1,0><<<dim3(NQKV / 128, MM / 128), 512, GEMM_DSMEM>>>(
        p_h_hi, p_h_lo, p_wqkvT_hi, p_wqkvT_lo,
        nullptr, nullptr, p_qkv, nullptr, nullptr, MM, NQKV, Cc);

    // 4. causal attention -> o bf16 split
    attn_kernel<<<dim3(Tt / 64, Hh, Bb), 128>>>(p_qkv, p_o_hi, p_o_lo);

    // 5. output projection + bias + residual -> x1 fp32
    mma_gemm_kernel<1,1,0,1,0><<<dim3(Cc / 128, MM / 128), 512, GEMM_DSMEM>>>(
        p_o_hi, p_o_lo, p_wpT_hi, p_wpT_lo,
        bp, x, p_x1, nullptr, nullptr, MM, Cc, Cc);

    // 6. LN2 -> bf16 split
    ln_kernel<<<MM, 128>>>(p_x1, g2, be2, p_h2_hi, p_h2_lo);

    // 7. FF1 + bias + relu -> ff bf16 split
    mma_gemm_kernel<1,0,1,0,1><<<dim3(FF / 128, MM / 128), 512, GEMM_DSMEM>>>(
        p_h2_hi, p_h2_lo, p_w1T_hi, p_w1T_lo,
        b1, nullptr, nullptr, p_ff_hi, p_ff_lo, MM, FF, Cc);

    // 8. FF2 + bias + residual -> final output fp32
    mma_gemm_kernel<1,1,0,1,0><<<dim3(Cc / 128, MM / 128), 512, GEMM_DSMEM>>>(
        p_ff_hi, p_ff_lo, p_w2T_hi, p_w2T_lo,
        b2, p_x1, out, nullptr, nullptr, MM, Cc, FF);
}

// round 10
// speedup vs baseline: 1.1348x; 1.1348x over previous
#include <cuda_runtime.h>
#include <cuda_fp16.h>
#include <cstdint>

// Problem dims
#define Bb   64
#define Tt   256
#define Cc   384
#define Hh   6
#define HSZ  64
#define MM   (Bb*Tt)     // 16384 tokens
#define NQKV (3*Cc)      // 1152
#define FF   (4*Cc)      // 1536

// ================= helpers =================
__device__ __forceinline__ uint32_t smem_u32(const void* p) {
    uint32_t a;
    asm("{ .reg .u64 t; cvta.to.shared.u64 t, %1; cvt.u32.u64 %0, t; }" : "=r"(a) : "l"(p));
    return a;
}
#define SMEM_SWIZZLE_128B(off) ((off) ^ (((off) >> 3) & 0x70))

#define CP_ASYNC16(dst, src) \
    asm volatile("cp.async.cg.shared.global [%0], [%1], 16;" :: "r"(dst), "l"(src))
#define CP_COMMIT() asm volatile("cp.async.commit_group;" ::: "memory")
#define CP_WAIT(n)  asm volatile("cp.async.wait_group %0;" :: "n"(n) : "memory")

#define LDSM_X4(r0, r1, r2, r3, addr) \
    asm volatile("ldmatrix.sync.aligned.m8n8.x4.shared.b16 {%0,%1,%2,%3}, [%4];" \
        : "=r"(r0), "=r"(r1), "=r"(r2), "=r"(r3) : "r"(addr))

#define MMA16816F16(d, a, b) \
    asm volatile("mma.sync.aligned.m16n8k16.row.col.f32.f16.f16.f32 " \
        "{%0,%1,%2,%3}, {%4,%5,%6,%7}, {%8,%9}, {%0,%1,%2,%3};" \
        : "+f"((d)[0]), "+f"((d)[1]), "+f"((d)[2]), "+f"((d)[3]) \
        : "r"((a)[0]), "r"((a)[1]), "r"((a)[2]), "r"((a)[3]), "r"((b)[0]), "r"((b)[1]))

// ================= scratch (device globals) =================
// activations: fp16 hi/lo split (hi+lo ~ exact fp32)
__device__ __align__(16) __half g_h_hi [MM*Cc];
__device__ __align__(16) __half g_h_lo [MM*Cc];
__device__ __align__(16) float  g_qkv  [MM*NQKV];
__device__ __align__(16) __half g_o_hi [MM*Cc];
__device__ __align__(16) __half g_o_lo [MM*Cc];
__device__ __align__(16) float  g_x1   [MM*Cc];
__device__ __align__(16) __half g_h2_hi[MM*Cc];
__device__ __align__(16) __half g_h2_lo[MM*Cc];
__device__ __align__(16) __half g_ff_hi[MM*FF];
__device__ __align__(16) __half g_ff_lo[MM*FF];
// weights: single fp16, transposed to [N][K]
__device__ __align__(16) __half g_wqkvT[NQKV*Cc];
__device__ __align__(16) __half g_wpT  [Cc*Cc];
__device__ __align__(16) __half g_w1T  [FF*Cc];
__device__ __align__(16) __half g_w2T  [Cc*FF];

__device__ __forceinline__ void split2h(float x, __half& hi, __half& lo) {
    hi = __float2half(x);
    lo = __float2half(x - __half2float(hi));
}

// ================= weight pack kernels (fp16 single) =================
__global__ void pack_qkvT_kernel(const float* __restrict__ Wq,
                                 const float* __restrict__ Wk,
                                 const float* __restrict__ Wv) {
    int idx = blockIdx.x * 256 + threadIdx.x;
    if (idx >= NQKV * Cc) return;
    int n = idx / Cc, k = idx % Cc;
    int which = n / Cc;
    int hd    = n % Cc;
    int h = hd / HSZ, d = hd % HSZ;
    const float* W = (which == 0) ? Wq : (which == 1) ? Wk : Wv;
    g_wqkvT[idx] = __float2half(W[(h * Cc + k) * HSZ + d]);
}

// transpose: out[n][k] = W[k*N + n]   (W is [K][N])
__global__ void convT_kernel(const float* __restrict__ W,
                             __half* __restrict__ out, int K, int N) {
    int idx = blockIdx.x * 256 + threadIdx.x;
    if (idx >= N * K) return;
    int n = idx / K, k = idx % K;
    out[idx] = __float2half(W[(size_t)k * N + n]);
}

// ================= LayerNorm -> fp16 hi/lo =================
__global__ void ln_kernel(const float* __restrict__ x,
                          const float* __restrict__ gamma,
                          const float* __restrict__ beta,
                          __half* __restrict__ yhi,
                          __half* __restrict__ ylo) {
    int row = blockIdx.x;
    const float* xr = x + (size_t)row * Cc;
    int tid = threadIdx.x;  // 128 threads, 3 elems each
    float v0 = xr[tid], v1 = xr[tid + 128], v2 = xr[tid + 256];
    float s  = v0 + v1 + v2;
    float sq = v0 * v0 + v1 * v1 + v2 * v2;
    #pragma unroll
    for (int o = 16; o > 0; o >>= 1) {
        s  += __shfl_down_sync(0xffffffffu, s,  o);
        sq += __shfl_down_sync(0xffffffffu, sq, o);
    }
    __shared__ float ss[4], sqs[4];
    int wid = tid >> 5, lid = tid & 31;
    if (lid == 0) { ss[wid] = s; sqs[wid] = sq; }
    __syncthreads();
    if (tid == 0) {
        float S  = ss[0] + ss[1] + ss[2] + ss[3];
        float SQ = sqs[0] + sqs[1] + sqs[2] + sqs[3];
        float mu  = S / (float)Cc;
        float var = SQ / (float)Cc - mu * mu;
        ss[0]  = mu;
        sqs[0] = rsqrtf(var + 1e-3f);
    }
    __syncthreads();
    float mu = ss[0], inv = sqs[0];
    size_t base = (size_t)row * Cc;
    float y0 = (v0 - mu) * inv * gamma[tid]       + beta[tid];
    float y1 = (v1 - mu) * inv * gamma[tid + 128] + beta[tid + 128];
    float y2 = (v2 - mu) * inv * gamma[tid + 256] + beta[tid + 256];
    split2h(y0, yhi[base + tid],       ylo[base + tid]);
    split2h(y1, yhi[base + tid + 128], ylo[base + tid + 128]);
    split2h(y2, yhi[base + tid + 256], ylo[base + tid + 256]);
}

// ================= mma.sync 2-term fp16 GEMM =================
// C[M,N] = A[M,K] * B^T, A=[M][K] fp16 hi/lo (exact), B=[N][K] fp16 (rounded).
// C = Ahi*B + Alo*B  (error = weight rounding only, ~2^-12 rel)
// CTA tile 128x128, BK=64, cp.async double buffer,
// 256 threads / 8 warps, each warp 64x32 (throughput-optimal per R6 data).
// SMEM per buffer: Ahi 16K | Alo 16K | B 16K = 48KB; two buffers = 96KB.
#define BUFSZ   49152
#define GEMM_DSMEM (1024 + 2 * BUFSZ)

__device__ __forceinline__ void load_tile_async(const __half* __restrict__ src,
                                                int row0, int k0, int Ktot,
                                                uint32_t dstbase, int tid) {
    #pragma unroll
    for (int j = 0; j < 4; j++) {
        int idx = tid + j * 256;         // 1024 x 16B = 128 rows x 128B
        int r = idx >> 3, c16 = idx & 7;
        const __half* g = src + (size_t)(row0 + r) * Ktot + k0 + c16 * 8;
        uint32_t s = dstbase + SMEM_SWIZZLE_128B((uint32_t)(r * 128 + c16 * 16));
        CP_ASYNC16(s, g);
    }
}

template<int BIAS, int RES, int RELU, int F32OUT, int HOUT>
__global__ __launch_bounds__(256)
void mma_gemm_kernel(const __half* __restrict__ Ahi, const __half* __restrict__ Alo,
                     const __half* __restrict__ Bw,
                     const float* __restrict__ bias, const float* __restrict__ res,
                     float* __restrict__ Cf,
                     __half* __restrict__ Chi, __half* __restrict__ Clo,
                     int M, int N, int K) {
    extern __shared__ char dsm[];
    uint32_t raw  = smem_u32(dsm);
    uint32_t base = (raw + 1023) & ~1023u;

    int tid = threadIdx.x, wid = tid >> 5, lane = tid & 31;
    int warp_m = (wid >> 2) * 64;   // 0 or 64
    int warp_n = (wid & 3) * 32;    // 0,32,64,96
    int m0 = blockIdx.y * 128, n0 = blockIdx.x * 128;
    int nch = K >> 6;

    float acc[4][4][4];
    #pragma unroll
    for (int a = 0; a < 4; a++)
        #pragma unroll
        for (int b = 0; b < 4; b++)
            #pragma unroll
            for (int c = 0; c < 4; c++) acc[a][b][c] = 0.f;

    // prologue: chunk 0 -> buffer 0
    load_tile_async(Ahi, m0, 0, K, base + 0,     tid);
    load_tile_async(Alo, m0, 0, K, base + 16384, tid);
    load_tile_async(Bw,  n0, 0, K, base + 32768, tid);
    CP_COMMIT();

    // ldmatrix lane mapping
    int q = lane >> 3, rin = lane & 7;
    int a_row_off = (q & 1) * 8 + rin;       // + mf*16
    int a_col_off = (q >> 1) * 8;            // + ks*16
    int b_row_off = (q >> 1) * 8 + rin;      // + nf2*16
    int b_col_off = (q & 1) * 8;             // + ks*16

    for (int i = 0; i < nch; i++) {
        if (i + 1 < nch) {
            uint32_t nb = base + ((i + 1) & 1) * BUFSZ;
            int k0 = (i + 1) << 6;
            load_tile_async(Ahi, m0, k0, K, nb + 0,     tid);
            load_tile_async(Alo, m0, k0, K, nb + 16384, tid);
            load_tile_async(Bw,  n0, k0, K, nb + 32768, tid);
            CP_COMMIT();
            CP_WAIT(1);
        } else {
            CP_WAIT(0);
        }
        __syncthreads();

        uint32_t buf = base + (i & 1) * BUFSZ;
        uint32_t sAhi = buf + 0, sAlo = buf + 16384, sB = buf + 32768;

        #pragma unroll
        for (int ks = 0; ks < 4; ks++) {
            uint32_t ahi[4][4], alo[4][4], bw[4][2];
            #pragma unroll
            for (int mf = 0; mf < 4; mf++) {
                uint32_t off = (uint32_t)((warp_m + mf * 16 + a_row_off) * 128 +
                                          (ks * 16 + a_col_off) * 2);
                LDSM_X4(ahi[mf][0], ahi[mf][1], ahi[mf][2], ahi[mf][3],
                        sAhi + SMEM_SWIZZLE_128B(off));
                LDSM_X4(alo[mf][0], alo[mf][1], alo[mf][2], alo[mf][3],
                        sAlo + SMEM_SWIZZLE_128B(off));
            }
            #pragma unroll
            for (int nf2 = 0; nf2 < 2; nf2++) {
                uint32_t off = (uint32_t)((warp_n + nf2 * 16 + b_row_off) * 128 +
                                          (ks * 16 + b_col_off) * 2);
                LDSM_X4(bw[nf2 * 2][0], bw[nf2 * 2][1], bw[nf2 * 2 + 1][0], bw[nf2 * 2 + 1][1],
                        sB + SMEM_SWIZZLE_128B(off));
            }
            #pragma unroll
            for (int mf = 0; mf < 4; mf++)
                #pragma unroll
                for (int nf = 0; nf < 4; nf++) MMA16816F16(acc[mf][nf], ahi[mf], bw[nf]);
            #pragma unroll
            for (int mf = 0; mf < 4; mf++)
                #pragma unroll
                for (int nf = 0; nf < 4; nf++) MMA16816F16(acc[mf][nf], alo[mf], bw[nf]);
        }
        __syncthreads();
    }

    // epilogue: direct register -> global with fused ops
    int tr = lane >> 2, tc = (lane & 3) * 2;
    #pragma unroll
    for (int mf = 0; mf < 4; mf++) {
        #pragma unroll
        for (int nf = 0; nf < 4; nf++) {
            int col = n0 + warp_n + nf * 8 + tc;
            #pragma unroll
            for (int half = 0; half < 2; half++) {
                int row = m0 + warp_m + mf * 16 + tr + half * 8;
                float v0 = acc[mf][nf][half * 2 + 0];
                float v1 = acc[mf][nf][half * 2 + 1];
                if (BIAS) { v0 += bias[col]; v1 += bias[col + 1]; }
                size_t oidx = (size_t)row * N + col;
                if (RES)  { v0 += res[oidx]; v1 += res[oidx + 1]; }
                if (RELU) { v0 = fmaxf(v0, 0.f); v1 = fmaxf(v1, 0.f); }
                if (F32OUT) {
                    Cf[oidx] = v0; Cf[oidx + 1] = v1;
                }
                if (HOUT) {
                    split2h(v0, Chi[oidx], Clo[oidx]);
                    split2h(v1, Chi[oidx + 1], Clo[oidx + 1]);
                }
            }
        }
    }
}

// ================= causal attention (fp32, lane-pair split over head dim) ====
// 128 threads/block: thread t handles query (t>>1), head-dim half (t&1)*32.
__global__ __launch_bounds__(128)
void attn_kernel(const float* __restrict__ qkv,
                 __half* __restrict__ ohi, __half* __restrict__ olo) {
    __shared__ float4 Kt[64][16];
    __shared__ float4 Vt[64][16];
    int b = blockIdx.z, h = blockIdx.y;
    int t = threadIdx.x;
    int qi = t >> 1, half = t & 1;
    int tq = blockIdx.x * 64 + qi;

    const float* qrow = qkv + ((size_t)(b * Tt + tq)) * NQKV + h * HSZ + half * 32;
    float4 q[8];
    #pragma unroll
    for (int i = 0; i < 8; i++) q[i] = *(const float4*)(qrow + 4 * i);

    float4 acc[8];
    #pragma unroll
    for (int i = 0; i < 8; i++) acc[i] = make_float4(0.f, 0.f, 0.f, 0.f);
    float m = -1e30f, l = 0.f;
    const float scale = 0.125f;

    for (int kt = 0; kt <= blockIdx.x; kt++) {
        {
            int lr = qi, lh = half;
            const float* kr = qkv + ((size_t)(b * Tt + kt * 64 + lr)) * NQKV + Cc + h * HSZ + lh * 32;
            const float* vr = kr + Cc;
            #pragma unroll
            for (int i = 0; i < 8; i++) {
                Kt[lr][lh * 8 + i] = *(const float4*)(kr + 4 * i);
                Vt[lr][lh * 8 + i] = *(const float4*)(vr + 4 * i);
            }
        }
        __syncthreads();

        bool diag = (kt == blockIdx.x);
        #pragma unroll 4
        for (int j = 0; j < 64; j++) {
            float sd = 0.f;
            #pragma unroll
            for (int i = 0; i < 8; i++) {
                float4 kk = Kt[j][half * 8 + i];
                sd += q[i].x * kk.x + q[i].y * kk.y + q[i].z * kk.z + q[i].w * kk.w;
            }
            sd += __shfl_xor_sync(0xffffffffu, sd, 1);
            sd *= scale;
            bool valid = !diag || (j <= qi);
            if (valid) {
                float p;
                if (sd > m) {
                    float corr = __expf(m - sd);
                    l *= corr;
                    #pragma unroll
                    for (int i = 0; i < 8; i++) {
                        acc[i].x *= corr; acc[i].y *= corr; acc[i].z *= corr; acc[i].w *= corr;
                    }
                    m = sd;
                    p = 1.f;
                } else {
                    p = __expf(sd - m);
                }
                l += p;
                #pragma unroll
                for (int i = 0; i < 8; i++) {
                    float4 vv = Vt[j][half * 8 + i];
                    acc[i].x += p * vv.x; acc[i].y += p * vv.y;
                    acc[i].z += p * vv.z; acc[i].w += p * vv.w;
                }
            }
            if (diag && j >= 63) break;
        }
        __syncthreads();
    }

    float inv = 1.f / l;
    size_t obase = ((size_t)(b * Tt + tq)) * Cc + h * HSZ + half * 32;
    #pragma unroll
    for (int i = 0; i < 8; i++) {
        float4 v = acc[i];
        split2h(v.x * inv, ohi[obase + 4 * i + 0], olo[obase + 4 * i + 0]);
        split2h(v.y * inv, ohi[obase + 4 * i + 1], olo[obase + 4 * i + 1]);
        split2h(v.z * inv, ohi[obase + 4 * i + 2], olo[obase + 4 * i + 2]);
        split2h(v.w * inv, ohi[obase + 4 * i + 3], olo[obase + 4 * i + 3]);
    }
}

// ================= host launch =================
template <typename T>
static T* sym_addr(const T* symbol) {
    void* p = nullptr;
    cudaGetSymbolAddress(&p, (const void*)symbol);
    return (T*)p;
}

extern "C" void kernel_launch(void* const* d_in, const int* in_sizes, int n_in,
                              void* d_out, int out_size) {
    const float* x   = (const float*)d_in[0];
    const float* Wq  = (const float*)d_in[1];
    const float* Wk  = (const float*)d_in[2];
    const float* Wv  = (const float*)d_in[3];
    const float* Wp  = (const float*)d_in[4];
    const float* bp  = (const float*)d_in[5];
    const float* W1  = (const float*)d_in[6];
    const float* b1  = (const float*)d_in[7];
    const float* W2  = (const float*)d_in[8];
    const float* b2  = (const float*)d_in[9];
    const float* g1  = (const float*)d_in[10];
    const float* be1 = (const float*)d_in[11];
    const float* g2  = (const float*)d_in[12];
    const float* be2 = (const float*)d_in[13];
    float* out = (float*)d_out;

    __half* p_h_hi  = sym_addr(g_h_hi);
    __half* p_h_lo  = sym_addr(g_h_lo);
    float*  p_qkv   = sym_addr(g_qkv);
    __half* p_o_hi  = sym_addr(g_o_hi);
    __half* p_o_lo  = sym_addr(g_o_lo);
    float*  p_x1    = sym_addr(g_x1);
    __half* p_h2_hi = sym_addr(g_h2_hi);
    __half* p_h2_lo = sym_addr(g_h2_lo);
    __half* p_ff_hi = sym_addr(g_ff_hi);
    __half* p_ff_lo = sym_addr(g_ff_lo);
    __half* p_wqkvT = sym_addr(g_wqkvT);
    __half* p_wpT   = sym_addr(g_wpT);
    __half* p_w1T   = sym_addr(g_w1T);
    __half* p_w2T   = sym_addr(g_w2T);

    cudaFuncSetAttribute(mma_gemm_kernel<0,0,0,1,0>, cudaFuncAttributeMaxDynamicSharedMemorySize, GEMM_DSMEM);
    cudaFuncSetAttribute(mma_gemm_kernel<1,1,0,1,0>, cudaFuncAttributeMaxDynamicSharedMemorySize, GEMM_DSMEM);
    cudaFuncSetAttribute(mma_gemm_kernel<1,0,1,0,1>, cudaFuncAttributeMaxDynamicSharedMemorySize, GEMM_DSMEM);

    // 1. weight packing (transposed, fp16 single)
    pack_qkvT_kernel<<<(NQKV * Cc + 255) / 256, 256>>>(Wq, Wk, Wv);
    convT_kernel<<<(Cc * Cc + 255) / 256, 256>>>(Wp, p_wpT, Cc, Cc);
    convT_kernel<<<(Cc * FF + 255) / 256, 256>>>(W1, p_w1T, Cc, FF);
    convT_kernel<<<(FF * Cc + 255) / 256, 256>>>(W2, p_w2T, FF, Cc);

    // 2. LN1 -> fp16 split
    ln_kernel<<<MM, 128>>>(x, g1, be1, p_h_hi, p_h_lo);

    // 3. fused QKV projection: [16384,384] x [384,1152] -> fp32 qkv
    mma_gemm_kernel<0,0,0,1,0><<<dim3(NQKV / 128, MM / 128), 256, GEMM_DSMEM>>>(
        p_h_hi, p_h_lo, p_wqkvT,
        nullptr, nullptr, p_qkv, nullptr, nullptr, MM, NQKV, Cc);

    // 4. causal attention -> o fp16 split
    attn_kernel<<<dim3(Tt / 64, Hh, Bb), 128>>>(p_qkv, p_o_hi, p_o_lo);

    // 5. output projection + bias + residual -> x1 fp32
    mma_gemm_kernel<1,1,0,1,0><<<dim3(Cc / 128, MM / 128), 256, GEMM_DSMEM>>>(
        p_o_hi, p_o_lo, p_wpT,
        bp, x, p_x1, nullptr, nullptr, MM, Cc, Cc);

    // 6. LN2 -> fp16 split
    ln_kernel<<<MM, 128>>>(p_x1, g2, be2, p_h2_hi, p_h2_lo);

    // 7. FF1 + bias + relu -> ff fp16 split
    mma_gemm_kernel<1,0,1,0,1><<<dim3(FF / 128, MM / 128), 256, GEMM_DSMEM>>>(
        p_h2_hi, p_h2_lo, p_w1T,
        b1, nullptr, nullptr, p_ff_hi, p_ff_lo, MM, FF, Cc);

    // 8. FF2 + bias + residual -> final output fp32
    mma_gemm_kernel<1,1,0,1,0><<<dim3(Cc / 128, MM / 128), 256, GEMM_DSMEM>>>(
        p_ff_hi, p_ff_lo, p_w2T,
        b2, p_x1, out, nullptr, nullptr, MM, Cc, FF);
}

// round 11
// speedup vs baseline: 1.5102x; 1.3308x over previous
#include <cuda_runtime.h>
#include <cuda_fp16.h>
#include <cstdint>

// Problem dims
#define Bb   64
#define Tt   256
#define Cc   384
#define Hh   6
#define HSZ  64
#define MM   (Bb*Tt)     // 16384 tokens
#define NQKV (3*Cc)      // 1152
#define FF   (4*Cc)      // 1536

// ================= helpers =================
__device__ __forceinline__ uint32_t smem_u32(const void* p) {
    uint32_t a;
    asm("{ .reg .u64 t; cvta.to.shared.u64 t, %1; cvt.u32.u64 %0, t; }" : "=r"(a) : "l"(p));
    return a;
}
#define SMEM_SWIZZLE_128B(off) ((off) ^ (((off) >> 3) & 0x70))

#define CP_ASYNC16(dst, src) \
    asm volatile("cp.async.cg.shared.global [%0], [%1], 16;" :: "r"(dst), "l"(src))
#define CP_COMMIT() asm volatile("cp.async.commit_group;" ::: "memory")
#define CP_WAIT(n)  asm volatile("cp.async.wait_group %0;" :: "n"(n) : "memory")

#define LDSM_X4(r0, r1, r2, r3, addr) \
    asm volatile("ldmatrix.sync.aligned.m8n8.x4.shared.b16 {%0,%1,%2,%3}, [%4];" \
        : "=r"(r0), "=r"(r1), "=r"(r2), "=r"(r3) : "r"(addr))

#define MMA16816F16(d, a, b) \
    asm volatile("mma.sync.aligned.m16n8k16.row.col.f32.f16.f16.f32 " \
        "{%0,%1,%2,%3}, {%4,%5,%6,%7}, {%8,%9}, {%0,%1,%2,%3};" \
        : "+f"((d)[0]), "+f"((d)[1]), "+f"((d)[2]), "+f"((d)[3]) \
        : "r"((a)[0]), "r"((a)[1]), "r"((a)[2]), "r"((a)[3]), "r"((b)[0]), "r"((b)[1]))

// ================= scratch (device globals) =================
// activations: single fp16
__device__ __align__(16) __half g_h  [MM*Cc];
__device__ __align__(16) float  g_qkv[MM*NQKV];
__device__ __align__(16) __half g_o  [MM*Cc];
__device__ __align__(16) float  g_x1 [MM*Cc];
__device__ __align__(16) __half g_h2 [MM*Cc];
__device__ __align__(16) __half g_ff [MM*FF];
// weights: single fp16, transposed to [N][K]
__device__ __align__(16) __half g_wqkvT[NQKV*Cc];
__device__ __align__(16) __half g_wpT  [Cc*Cc];
__device__ __align__(16) __half g_w1T  [FF*Cc];
__device__ __align__(16) __half g_w2T  [Cc*FF];

// ================= weight pack kernels (fp16 single) =================
__global__ void pack_qkvT_kernel(const float* __restrict__ Wq,
                                 const float* __restrict__ Wk,
                                 const float* __restrict__ Wv) {
    int idx = blockIdx.x * 256 + threadIdx.x;
    if (idx >= NQKV * Cc) return;
    int n = idx / Cc, k = idx % Cc;
    int which = n / Cc;
    int hd    = n % Cc;
    int h = hd / HSZ, d = hd % HSZ;
    const float* W = (which == 0) ? Wq : (which == 1) ? Wk : Wv;
    g_wqkvT[idx] = __float2half(W[(h * Cc + k) * HSZ + d]);
}

// transpose: out[n][k] = W[k*N + n]   (W is [K][N])
__global__ void convT_kernel(const float* __restrict__ W,
                             __half* __restrict__ out, int K, int N) {
    int idx = blockIdx.x * 256 + threadIdx.x;
    if (idx >= N * K) return;
    int n = idx / K, k = idx % K;
    out[idx] = __float2half(W[(size_t)k * N + n]);
}

// ================= LayerNorm -> fp16 =================
__global__ void ln_kernel(const float* __restrict__ x,
                          const float* __restrict__ gamma,
                          const float* __restrict__ beta,
                          __half* __restrict__ y) {
    int row = blockIdx.x;
    const float* xr = x + (size_t)row * Cc;
    int tid = threadIdx.x;  // 128 threads, 3 elems each
    float v0 = xr[tid], v1 = xr[tid + 128], v2 = xr[tid + 256];
    float s  = v0 + v1 + v2;
    float sq = v0 * v0 + v1 * v1 + v2 * v2;
    #pragma unroll
    for (int o = 16; o > 0; o >>= 1) {
        s  += __shfl_down_sync(0xffffffffu, s,  o);
        sq += __shfl_down_sync(0xffffffffu, sq, o);
    }
    __shared__ float ss[4], sqs[4];
    int wid = tid >> 5, lid = tid & 31;
    if (lid == 0) { ss[wid] = s; sqs[wid] = sq; }
    __syncthreads();
    if (tid == 0) {
        float S  = ss[0] + ss[1] + ss[2] + ss[3];
        float SQ = sqs[0] + sqs[1] + sqs[2] + sqs[3];
        float mu  = S / (float)Cc;
        float var = SQ / (float)Cc - mu * mu;
        ss[0]  = mu;
        sqs[0] = rsqrtf(var + 1e-3f);
    }
    __syncthreads();
    float mu = ss[0], inv = sqs[0];
    size_t base = (size_t)row * Cc;
    y[base + tid]       = __float2half((v0 - mu) * inv * gamma[tid]       + beta[tid]);
    y[base + tid + 128] = __float2half((v1 - mu) * inv * gamma[tid + 128] + beta[tid + 128]);
    y[base + tid + 256] = __float2half((v2 - mu) * inv * gamma[tid + 256] + beta[tid + 256]);
}

// ================= mma.sync fp16 GEMM =================
// C[M,N] = A[M,K] * B^T, A=[M][K] fp16, B=[N][K] fp16 (both RN-rounded).
// CTA tile 128x128, BK=64, cp.async double buffer,
// 256 threads / 8 warps, each warp 64x32.
// SMEM per buffer: A 16K | B 16K = 32KB; two buffers = 64KB -> 3 CTA/SM.
#define BUFSZ   32768
#define GEMM_DSMEM (1024 + 2 * BUFSZ)

__device__ __forceinline__ void load_tile_async(const __half* __restrict__ src,
                                                int row0, int k0, int Ktot,
                                                uint32_t dstbase, int tid) {
    #pragma unroll
    for (int j = 0; j < 4; j++) {
        int idx = tid + j * 256;         // 1024 x 16B = 128 rows x 128B
        int r = idx >> 3, c16 = idx & 7;
        const __half* g = src + (size_t)(row0 + r) * Ktot + k0 + c16 * 8;
        uint32_t s = dstbase + SMEM_SWIZZLE_128B((uint32_t)(r * 128 + c16 * 16));
        CP_ASYNC16(s, g);
    }
}

template<int BIAS, int RES, int RELU, int F32OUT, int HOUT>
__global__ __launch_bounds__(256)
void mma_gemm_kernel(const __half* __restrict__ A,
                     const __half* __restrict__ Bw,
                     const float* __restrict__ bias, const float* __restrict__ res,
                     float* __restrict__ Cf, __half* __restrict__ Ch,
                     int M, int N, int K) {
    extern __shared__ char dsm[];
    uint32_t raw  = smem_u32(dsm);
    uint32_t base = (raw + 1023) & ~1023u;

    int tid = threadIdx.x, wid = tid >> 5, lane = tid & 31;
    int warp_m = (wid >> 2) * 64;   // 0 or 64
    int warp_n = (wid & 3) * 32;    // 0,32,64,96
    int m0 = blockIdx.y * 128, n0 = blockIdx.x * 128;
    int nch = K >> 6;

    float acc[4][4][4];
    #pragma unroll
    for (int a = 0; a < 4; a++)
        #pragma unroll
        for (int b = 0; b < 4; b++)
            #pragma unroll
            for (int c = 0; c < 4; c++) acc[a][b][c] = 0.f;

    // prologue: chunk 0 -> buffer 0
    load_tile_async(A,  m0, 0, K, base + 0,     tid);
    load_tile_async(Bw, n0, 0, K, base + 16384, tid);
    CP_COMMIT();

    // ldmatrix lane mapping
    int q = lane >> 3, rin = lane & 7;
    int a_row_off = (q & 1) * 8 + rin;       // + mf*16
    int a_col_off = (q >> 1) * 8;            // + ks*16
    int b_row_off = (q >> 1) * 8 + rin;      // + nf2*16
    int b_col_off = (q & 1) * 8;             // + ks*16

    for (int i = 0; i < nch; i++) {
        if (i + 1 < nch) {
            uint32_t nb = base + ((i + 1) & 1) * BUFSZ;
            int k0 = (i + 1) << 6;
            load_tile_async(A,  m0, k0, K, nb + 0,     tid);
            load_tile_async(Bw, n0, k0, K, nb + 16384, tid);
            CP_COMMIT();
            CP_WAIT(1);
        } else {
            CP_WAIT(0);
        }
        __syncthreads();

        uint32_t buf = base + (i & 1) * BUFSZ;
        uint32_t sA = buf + 0, sB = buf + 16384;

        #pragma unroll
        for (int ks = 0; ks < 4; ks++) {
            uint32_t af[4][4], bw[4][2];
            #pragma unroll
            for (int mf = 0; mf < 4; mf++) {
                uint32_t off = (uint32_t)((warp_m + mf * 16 + a_row_off) * 128 +
                                          (ks * 16 + a_col_off) * 2);
                LDSM_X4(af[mf][0], af[mf][1], af[mf][2], af[mf][3],
                        sA + SMEM_SWIZZLE_128B(off));
            }
            #pragma unroll
            for (int nf2 = 0; nf2 < 2; nf2++) {
                uint32_t off = (uint32_t)((warp_n + nf2 * 16 + b_row_off) * 128 +
                                          (ks * 16 + b_col_off) * 2);
                LDSM_X4(bw[nf2 * 2][0], bw[nf2 * 2][1], bw[nf2 * 2 + 1][0], bw[nf2 * 2 + 1][1],
                        sB + SMEM_SWIZZLE_128B(off));
            }
            #pragma unroll
            for (int mf = 0; mf < 4; mf++)
                #pragma unroll
                for (int nf = 0; nf < 4; nf++) MMA16816F16(acc[mf][nf], af[mf], bw[nf]);
        }
        __syncthreads();
    }

    // epilogue: direct register -> global with fused ops
    int tr = lane >> 2, tc = (lane & 3) * 2;
    #pragma unroll
    for (int mf = 0; mf < 4; mf++) {
        #pragma unroll
        for (int nf = 0; nf < 4; nf++) {
            int col = n0 + warp_n + nf * 8 + tc;
            #pragma unroll
            for (int half = 0; half < 2; half++) {
                int row = m0 + warp_m + mf * 16 + tr + half * 8;
                float v0 = acc[mf][nf][half * 2 + 0];
                float v1 = acc[mf][nf][half * 2 + 1];
                if (BIAS) { v0 += bias[col]; v1 += bias[col + 1]; }
                size_t oidx = (size_t)row * N + col;
                if (RES)  { v0 += res[oidx]; v1 += res[oidx + 1]; }
                if (RELU) { v0 = fmaxf(v0, 0.f); v1 = fmaxf(v1, 0.f); }
                if (F32OUT) {
                    Cf[oidx] = v0; Cf[oidx + 1] = v1;
                }
                if (HOUT) {
                    Ch[oidx]     = __float2half(v0);
                    Ch[oidx + 1] = __float2half(v1);
                }
            }
        }
    }
}

// ================= causal attention (fp32, lane-pair split over head dim) ====
// 128 threads/block: thread t handles query (t>>1), head-dim half (t&1)*32.
__global__ __launch_bounds__(128)
void attn_kernel(const float* __restrict__ qkv, __half* __restrict__ o) {
    __shared__ float4 Kt[64][16];
    __shared__ float4 Vt[64][16];
    int b = blockIdx.z, h = blockIdx.y;
    int t = threadIdx.x;
    int qi = t >> 1, half = t & 1;
    int tq = blockIdx.x * 64 + qi;

    const float* qrow = qkv + ((size_t)(b * Tt + tq)) * NQKV + h * HSZ + half * 32;
    float4 q[8];
    #pragma unroll
    for (int i = 0; i < 8; i++) q[i] = *(const float4*)(qrow + 4 * i);

    float4 acc[8];
    #pragma unroll
    for (int i = 0; i < 8; i++) acc[i] = make_float4(0.f, 0.f, 0.f, 0.f);
    float m = -1e30f, l = 0.f;
    const float scale = 0.125f;

    for (int kt = 0; kt <= blockIdx.x; kt++) {
        {
            int lr = qi, lh = half;
            const float* kr = qkv + ((size_t)(b * Tt + kt * 64 + lr)) * NQKV + Cc + h * HSZ + lh * 32;
            const float* vr = kr + Cc;
            #pragma unroll
            for (int i = 0; i < 8; i++) {
                Kt[lr][lh * 8 + i] = *(const float4*)(kr + 4 * i);
                Vt[lr][lh * 8 + i] = *(const float4*)(vr + 4 * i);
            }
        }
        __syncthreads();

        bool diag = (kt == blockIdx.x);
        #pragma unroll 4
        for (int j = 0; j < 64; j++) {
            float sd = 0.f;
            #pragma unroll
            for (int i = 0; i < 8; i++) {
                float4 kk = Kt[j][half * 8 + i];
                sd += q[i].x * kk.x + q[i].y * kk.y + q[i].z * kk.z + q[i].w * kk.w;
            }
            sd += __shfl_xor_sync(0xffffffffu, sd, 1);
            sd *= scale;
            bool valid = !diag || (j <= qi);
            if (valid) {
                float p;
                if (sd > m) {
                    float corr = __expf(m - sd);
                    l *= corr;
                    #pragma unroll
                    for (int i = 0; i < 8; i++) {
                        acc[i].x *= corr; acc[i].y *= corr; acc[i].z *= corr; acc[i].w *= corr;
                    }
                    m = sd;
                    p = 1.f;
                } else {
                    p = __expf(sd - m);
                }
                l += p;
                #pragma unroll
                for (int i = 0; i < 8; i++) {
                    float4 vv = Vt[j][half * 8 + i];
                    acc[i].x += p * vv.x; acc[i].y += p * vv.y;
                    acc[i].z += p * vv.z; acc[i].w += p * vv.w;
                }
            }
            if (diag && j >= 63) break;
        }
        __syncthreads();
    }

    float inv = 1.f / l;
    size_t obase = ((size_t)(b * Tt + tq)) * Cc + h * HSZ + half * 32;
    #pragma unroll
    for (int i = 0; i < 8; i++) {
        float4 v = acc[i];
        o[obase + 4 * i + 0] = __float2half(v.x * inv);
        o[obase + 4 * i + 1] = __float2half(v.y * inv);
        o[obase + 4 * i + 2] = __float2half(v.z * inv);
        o[obase + 4 * i + 3] = __float2half(v.w * inv);
    }
}

// ================= host launch =================
template <typename T>
static T* sym_addr(const T* symbol) {
    void* p = nullptr;
    cudaGetSymbolAddress(&p, (const void*)symbol);
    return (T*)p;
}

extern "C" void kernel_launch(void* const* d_in, const int* in_sizes, int n_in,
                              void* d_out, int out_size) {
    const float* x   = (const float*)d_in[0];
    const float* Wq  = (const float*)d_in[1];
    const float* Wk  = (const float*)d_in[2];
    const float* Wv  = (const float*)d_in[3];
    const float* Wp  = (const float*)d_in[4];
    const float* bp  = (const float*)d_in[5];
    const float* W1  = (const float*)d_in[6];
    const float* b1  = (const float*)d_in[7];
    const float* W2  = (const float*)d_in[8];
    const float* b2  = (const float*)d_in[9];
    const float* g1  = (const float*)d_in[10];
    const float* be1 = (const float*)d_in[11];
    const float* g2  = (const float*)d_in[12];
    const float* be2 = (const float*)d_in[13];
    float* out = (float*)d_out;

    __half* p_h   = sym_addr(g_h);
    float*  p_qkv = sym_addr(g_qkv);
    __half* p_o   = sym_addr(g_o);
    float*  p_x1  = sym_addr(g_x1);
    __half* p_h2  = sym_addr(g_h2);
    __half* p_ff  = sym_addr(g_ff);
    __half* p_wqkvT = sym_addr(g_wqkvT);
    __half* p_wpT   = sym_addr(g_wpT);
    __half* p_w1T   = sym_addr(g_w1T);
    __half* p_w2T   = sym_addr(g_w2T);

    cudaFuncSetAttribute(mma_gemm_kernel<0,0,0,1,0>, cudaFuncAttributeMaxDynamicSharedMemorySize, GEMM_DSMEM);
    cudaFuncSetAttribute(mma_gemm_kernel<1,1,0,1,0>, cudaFuncAttributeMaxDynamicSharedMemorySize, GEMM_DSMEM);
    cudaFuncSetAttribute(mma_gemm_kernel<1,0,1,0,1>, cudaFuncAttributeMaxDynamicSharedMemorySize, GEMM_DSMEM);

    // 1. weight packing (transposed, fp16)
    pack_qkvT_kernel<<<(NQKV * Cc + 255) / 256, 256>>>(Wq, Wk, Wv);
    convT_kernel<<<(Cc * Cc + 255) / 256, 256>>>(Wp, p_wpT, Cc, Cc);
    convT_kernel<<<(Cc * FF + 255) / 256, 256>>>(W1, p_w1T, Cc, FF);
    convT_kernel<<<(FF * Cc + 255) / 256, 256>>>(W2, p_w2T, FF, Cc);

    // 2. LN1 -> fp16
    ln_kernel<<<MM, 128>>>(x, g1, be1, p_h);

    // 3. fused QKV projection: [16384,384] x [384,1152] -> fp32 qkv
    mma_gemm_kernel<0,0,0,1,0><<<dim3(NQKV / 128, MM / 128), 256, GEMM_DSMEM>>>(
        p_h, p_wqkvT, nullptr, nullptr, p_qkv, nullptr, MM, NQKV, Cc);

    // 4. causal attention -> o fp16
    attn_kernel<<<dim3(Tt / 64, Hh, Bb), 128>>>(p_qkv, p_o);

    // 5. output projection + bias + residual -> x1 fp32
    mma_gemm_kernel<1,1,0,1,0><<<dim3(Cc / 128, MM / 128), 256, GEMM_DSMEM>>>(
        p_o, p_wpT, bp, x, p_x1, nullptr, MM, Cc, Cc);

    // 6. LN2 -> fp16
    ln_kernel<<<MM, 128>>>(p_x1, g2, be2, p_h2);

    // 7. FF1 + bias + relu -> ff fp16
    mma_gemm_kernel<1,0,1,0,1><<<dim3(FF / 128, MM / 128), 256, GEMM_DSMEM>>>(
        p_h2, p_w1T, b1, nullptr, nullptr, p_ff, MM, FF, Cc);

    // 8. FF2 + bias + residual -> final output fp32
    mma_gemm_kernel<1,1,0,1,0><<<dim3(Cc / 128, MM / 128), 256, GEMM_DSMEM>>>(
        p_ff, p_w2T, b2, p_x1, out, nullptr, MM, Cc, FF);
}

// round 12
// speedup vs baseline: 2.6874x; 1.7795x over previous
#include <cuda_runtime.h>
#include <cuda_fp16.h>
#include <cstdint>

// Problem dims
#define Bb   64
#define Tt   256
#define Cc   384
#define Hh   6
#define HSZ  64
#define MM   (Bb*Tt)     // 16384 tokens
#define NQKV (3*Cc)      // 1152
#define FF   (4*Cc)      // 1536

// ================= helpers =================
__device__ __forceinline__ uint32_t smem_u32(const void* p) {
    uint32_t a;
    asm("{ .reg .u64 t; cvta.to.shared.u64 t, %1; cvt.u32.u64 %0, t; }" : "=r"(a) : "l"(p));
    return a;
}
#define SMEM_SWIZZLE_128B(off) ((off) ^ (((off) >> 3) & 0x70))

#define CP_ASYNC16(dst, src) \
    asm volatile("cp.async.cg.shared.global [%0], [%1], 16;" :: "r"(dst), "l"(src))
#define CP_COMMIT() asm volatile("cp.async.commit_group;" ::: "memory")
#define CP_WAIT(n)  asm volatile("cp.async.wait_group %0;" :: "n"(n) : "memory")

#define LDSM_X4(r0, r1, r2, r3, addr) \
    asm volatile("ldmatrix.sync.aligned.m8n8.x4.shared.b16 {%0,%1,%2,%3}, [%4];" \
        : "=r"(r0), "=r"(r1), "=r"(r2), "=r"(r3) : "r"(addr))

#define LDSM_X4_T(r0, r1, r2, r3, addr) \
    asm volatile("ldmatrix.sync.aligned.m8n8.x4.trans.shared.b16 {%0,%1,%2,%3}, [%4];" \
        : "=r"(r0), "=r"(r1), "=r"(r2), "=r"(r3) : "r"(addr))

#define MMA16816F16(d, a, b) \
    asm volatile("mma.sync.aligned.m16n8k16.row.col.f32.f16.f16.f32 " \
        "{%0,%1,%2,%3}, {%4,%5,%6,%7}, {%8,%9}, {%0,%1,%2,%3};" \
        : "+f"((d)[0]), "+f"((d)[1]), "+f"((d)[2]), "+f"((d)[3]) \
        : "r"((a)[0]), "r"((a)[1]), "r"((a)[2]), "r"((a)[3]), "r"((b)[0]), "r"((b)[1]))

__device__ __forceinline__ uint32_t pack_h2(float a, float b) {
    __half2 h = __floats2half2_rn(a, b);
    return *reinterpret_cast<uint32_t*>(&h);
}

// ================= scratch (device globals) =================
__device__ __align__(16) __half g_h   [MM*Cc];
__device__ __align__(16) __half g_qkvh[MM*NQKV];   // fp16 q|k|v
__device__ __align__(16) __half g_o   [MM*Cc];
__device__ __align__(16) float  g_x1  [MM*Cc];
__device__ __align__(16) __half g_h2  [MM*Cc];
__device__ __align__(16) __half g_ff  [MM*FF];
// weights: single fp16, transposed to [N][K]
__device__ __align__(16) __half g_wqkvT[NQKV*Cc];
__device__ __align__(16) __half g_wpT  [Cc*Cc];
__device__ __align__(16) __half g_w1T  [FF*Cc];
__device__ __align__(16) __half g_w2T  [Cc*FF];

// ================= weight pack kernels =================
__global__ void pack_qkvT_kernel(const float* __restrict__ Wq,
                                 const float* __restrict__ Wk,
                                 const float* __restrict__ Wv) {
    int idx = blockIdx.x * 256 + threadIdx.x;
    if (idx >= NQKV * Cc) return;
    int n = idx / Cc, k = idx % Cc;
    int which = n / Cc;
    int hd    = n % Cc;
    int h = hd / HSZ, d = hd % HSZ;
    const float* W = (which == 0) ? Wq : (which == 1) ? Wk : Wv;
    g_wqkvT[idx] = __float2half(W[(h * Cc + k) * HSZ + d]);
}

__global__ void convT_kernel(const float* __restrict__ W,
                             __half* __restrict__ out, int K, int N) {
    int idx = blockIdx.x * 256 + threadIdx.x;
    if (idx >= N * K) return;
    int n = idx / K, k = idx % K;
    out[idx] = __float2half(W[(size_t)k * N + n]);
}

// ================= LayerNorm -> fp16 =================
__global__ void ln_kernel(const float* __restrict__ x,
                          const float* __restrict__ gamma,
                          const float* __restrict__ beta,
                          __half* __restrict__ y) {
    int row = blockIdx.x;
    const float* xr = x + (size_t)row * Cc;
    int tid = threadIdx.x;
    float v0 = xr[tid], v1 = xr[tid + 128], v2 = xr[tid + 256];
    float s  = v0 + v1 + v2;
    float sq = v0 * v0 + v1 * v1 + v2 * v2;
    #pragma unroll
    for (int o = 16; o > 0; o >>= 1) {
        s  += __shfl_down_sync(0xffffffffu, s,  o);
        sq += __shfl_down_sync(0xffffffffu, sq, o);
    }
    __shared__ float ss[4], sqs[4];
    int wid = tid >> 5, lid = tid & 31;
    if (lid == 0) { ss[wid] = s; sqs[wid] = sq; }
    __syncthreads();
    if (tid == 0) {
        float S  = ss[0] + ss[1] + ss[2] + ss[3];
        float SQ = sqs[0] + sqs[1] + sqs[2] + sqs[3];
        float mu  = S / (float)Cc;
        float var = SQ / (float)Cc - mu * mu;
        ss[0]  = mu;
        sqs[0] = rsqrtf(var + 1e-3f);
    }
    __syncthreads();
    float mu = ss[0], inv = sqs[0];
    size_t base = (size_t)row * Cc;
    y[base + tid]       = __float2half((v0 - mu) * inv * gamma[tid]       + beta[tid]);
    y[base + tid + 128] = __float2half((v1 - mu) * inv * gamma[tid + 128] + beta[tid + 128]);
    y[base + tid + 256] = __float2half((v2 - mu) * inv * gamma[tid + 256] + beta[tid + 256]);
}

// ================= mma.sync fp16 GEMM (same as R10 passing version) =========
#define BUFSZ   32768
#define GEMM_DSMEM (1024 + 2 * BUFSZ)

__device__ __forceinline__ void load_tile_async(const __half* __restrict__ src,
                                                int row0, int k0, int Ktot,
                                                uint32_t dstbase, int tid) {
    #pragma unroll
    for (int j = 0; j < 4; j++) {
        int idx = tid + j * 256;
        int r = idx >> 3, c16 = idx & 7;
        const __half* g = src + (size_t)(row0 + r) * Ktot + k0 + c16 * 8;
        uint32_t s = dstbase + SMEM_SWIZZLE_128B((uint32_t)(r * 128 + c16 * 16));
        CP_ASYNC16(s, g);
    }
}

template<int BIAS, int RES, int RELU, int F32OUT, int HOUT>
__global__ __launch_bounds__(256)
void mma_gemm_kernel(const __half* __restrict__ A,
                     const __half* __restrict__ Bw,
                     const float* __restrict__ bias, const float* __restrict__ res,
                     float* __restrict__ Cf, __half* __restrict__ Ch,
                     int M, int N, int K) {
    extern __shared__ char dsm[];
    uint32_t raw  = smem_u32(dsm);
    uint32_t base = (raw + 1023) & ~1023u;

    int tid = threadIdx.x, wid = tid >> 5, lane = tid & 31;
    int warp_m = (wid >> 2) * 64;
    int warp_n = (wid & 3) * 32;
    int m0 = blockIdx.y * 128, n0 = blockIdx.x * 128;
    int nch = K >> 6;

    float acc[4][4][4];
    #pragma unroll
    for (int a = 0; a < 4; a++)
        #pragma unroll
        for (int b = 0; b < 4; b++)
            #pragma unroll
            for (int c = 0; c < 4; c++) acc[a][b][c] = 0.f;

    load_tile_async(A,  m0, 0, K, base + 0,     tid);
    load_tile_async(Bw, n0, 0, K, base + 16384, tid);
    CP_COMMIT();

    int q = lane >> 3, rin = lane & 7;
    int a_row_off = (q & 1) * 8 + rin;
    int a_col_off = (q >> 1) * 8;
    int b_row_off = (q >> 1) * 8 + rin;
    int b_col_off = (q & 1) * 8;

    for (int i = 0; i < nch; i++) {
        if (i + 1 < nch) {
            uint32_t nb = base + ((i + 1) & 1) * BUFSZ;
            int k0 = (i + 1) << 6;
            load_tile_async(A,  m0, k0, K, nb + 0,     tid);
            load_tile_async(Bw, n0, k0, K, nb + 16384, tid);
            CP_COMMIT();
            CP_WAIT(1);
        } else {
            CP_WAIT(0);
        }
        __syncthreads();

        uint32_t buf = base + (i & 1) * BUFSZ;
        uint32_t sA = buf + 0, sB = buf + 16384;

        #pragma unroll
        for (int ks = 0; ks < 4; ks++) {
            uint32_t af[4][4], bw[4][2];
            #pragma unroll
            for (int mf = 0; mf < 4; mf++) {
                uint32_t off = (uint32_t)((warp_m + mf * 16 + a_row_off) * 128 +
                                          (ks * 16 + a_col_off) * 2);
                LDSM_X4(af[mf][0], af[mf][1], af[mf][2], af[mf][3],
                        sA + SMEM_SWIZZLE_128B(off));
            }
            #pragma unroll
            for (int nf2 = 0; nf2 < 2; nf2++) {
                uint32_t off = (uint32_t)((warp_n + nf2 * 16 + b_row_off) * 128 +
                                          (ks * 16 + b_col_off) * 2);
                LDSM_X4(bw[nf2 * 2][0], bw[nf2 * 2][1], bw[nf2 * 2 + 1][0], bw[nf2 * 2 + 1][1],
                        sB + SMEM_SWIZZLE_128B(off));
            }
            #pragma unroll
            for (int mf = 0; mf < 4; mf++)
                #pragma unroll
                for (int nf = 0; nf < 4; nf++) MMA16816F16(acc[mf][nf], af[mf], bw[nf]);
        }
        __syncthreads();
    }

    int tr = lane >> 2, tc = (lane & 3) * 2;
    #pragma unroll
    for (int mf = 0; mf < 4; mf++) {
        #pragma unroll
        for (int nf = 0; nf < 4; nf++) {
            int col = n0 + warp_n + nf * 8 + tc;
            #pragma unroll
            for (int half = 0; half < 2; half++) {
                int row = m0 + warp_m + mf * 16 + tr + half * 8;
                float v0 = acc[mf][nf][half * 2 + 0];
                float v1 = acc[mf][nf][half * 2 + 1];
                if (BIAS) { v0 += bias[col]; v1 += bias[col + 1]; }
                size_t oidx = (size_t)row * N + col;
                if (RES)  { v0 += res[oidx]; v1 += res[oidx + 1]; }
                if (RELU) { v0 = fmaxf(v0, 0.f); v1 = fmaxf(v1, 0.f); }
                if (F32OUT) { Cf[oidx] = v0; Cf[oidx + 1] = v1; }
                if (HOUT) {
                    Ch[oidx]     = __float2half(v0);
                    Ch[oidx + 1] = __float2half(v1);
                }
            }
        }
    }
}

// ================= flash attention (mma.sync fp16) =================
// grid (T/64, H, B), 128 threads (4 warps). Warp w owns q rows [w*16, w*16+16).
// smem: Q | K0 | K1 | V0 | V1, each 64x64 fp16 = 8KB (1024-aligned).
__device__ __forceinline__ void fattn_load_kv(const __half* __restrict__ qkv,
                                              int b, int h, int kt,
                                              uint32_t kbase, uint32_t vbase, int tid) {
    #pragma unroll
    for (int j = 0; j < 4; j++) {
        int idx = tid + j * 128;
        int r = idx >> 3, c = idx & 7;
        const __half* ks = qkv + (size_t)(b * Tt + kt * 64 + r) * NQKV + Cc + h * HSZ + c * 8;
        CP_ASYNC16(kbase + SMEM_SWIZZLE_128B((uint32_t)(r * 128 + c * 16)), ks);
    }
    #pragma unroll
    for (int j = 0; j < 4; j++) {
        int idx = tid + j * 128;
        int r = idx >> 3, c = idx & 7;
        const __half* vs = qkv + (size_t)(b * Tt + kt * 64 + r) * NQKV + 2 * Cc + h * HSZ + c * 8;
        CP_ASYNC16(vbase + SMEM_SWIZZLE_128B((uint32_t)(r * 128 + c * 16)), vs);
    }
}

__global__ __launch_bounds__(128)
void fattn_kernel(const __half* __restrict__ qkv, __half* __restrict__ o) {
    __shared__ __align__(1024) __half smem[5 * 4096];
    int tid = threadIdx.x, wid = tid >> 5, lane = tid & 31;
    int b = blockIdx.z, h = blockIdx.y, qt = blockIdx.x;
    uint32_t sbase = smem_u32(smem);
    uint32_t qb = sbase;
    uint32_t kb0 = sbase + 8192,  kb1 = sbase + 16384;
    uint32_t vb0 = sbase + 24576, vb1 = sbase + 32768;

    // prologue: Q tile + KV tile 0
    #pragma unroll
    for (int j = 0; j < 4; j++) {
        int idx = tid + j * 128;
        int r = idx >> 3, c = idx & 7;
        const __half* src = qkv + (size_t)(b * Tt + qt * 64 + r) * NQKV + h * HSZ + c * 8;
        CP_ASYNC16(qb + SMEM_SWIZZLE_128B((uint32_t)(r * 128 + c * 16)), src);
    }
    fattn_load_kv(qkv, b, h, 0, kb0, vb0, tid);
    CP_COMMIT();
    CP_WAIT(0);
    __syncthreads();

    int q8 = lane >> 3, rin = lane & 7;
    int a_row = (q8 & 1) * 8 + rin, a_col = (q8 >> 1) * 8;
    int b_row = (q8 >> 1) * 8 + rin, b_col = (q8 & 1) * 8;
    int vm = lane >> 3;
    int v_row = (vm & 1) * 8 + (lane & 7);
    int v_col = (vm >> 1) * 8;
    int tg = lane & 3, gid = lane >> 2;

    // Q fragments (held in registers for whole kernel)
    uint32_t qf[4][4];
    #pragma unroll
    for (int kc = 0; kc < 4; kc++)
        LDSM_X4(qf[kc][0], qf[kc][1], qf[kc][2], qf[kc][3],
                qb + SMEM_SWIZZLE_128B((uint32_t)((wid * 16 + a_row) * 128 + (kc * 16 + a_col) * 2)));

    float oacc[8][4];
    #pragma unroll
    for (int d = 0; d < 8; d++)
        #pragma unroll
        for (int e = 0; e < 4; e++) oacc[d][e] = 0.f;
    float m0 = -1e30f, m1 = -1e30f, l0 = 0.f, l1 = 0.f;

    for (int kt = 0; kt <= qt; kt++) {
        uint32_t kb = (kt & 1) ? kb1 : kb0;
        uint32_t vb = (kt & 1) ? vb1 : vb0;
        if (kt < qt) {
            fattn_load_kv(qkv, b, h, kt + 1, (kt & 1) ? kb0 : kb1, (kt & 1) ? vb0 : vb1, tid);
            CP_COMMIT();
        }

        // ---- S = Q K^T ----
        float sacc[8][4];
        #pragma unroll
        for (int n = 0; n < 8; n++)
            #pragma unroll
            for (int e = 0; e < 4; e++) sacc[n][e] = 0.f;
        #pragma unroll
        for (int kc = 0; kc < 4; kc++) {
            uint32_t bw[8][2];
            #pragma unroll
            for (int nf2 = 0; nf2 < 4; nf2++)
                LDSM_X4(bw[nf2 * 2][0], bw[nf2 * 2][1], bw[nf2 * 2 + 1][0], bw[nf2 * 2 + 1][1],
                        kb + SMEM_SWIZZLE_128B((uint32_t)((nf2 * 16 + b_row) * 128 + (kc * 16 + b_col) * 2)));
            #pragma unroll
            for (int nf = 0; nf < 8; nf++) MMA16816F16(sacc[nf], qf[kc], bw[nf]);
        }

        // scale + causal mask (diag tile only)
        #pragma unroll
        for (int nf = 0; nf < 8; nf++)
            #pragma unroll
            for (int e = 0; e < 4; e++) sacc[nf][e] *= 0.125f;
        if (kt == qt) {
            int r0 = wid * 16 + gid, r1 = r0 + 8;
            #pragma unroll
            for (int nf = 0; nf < 8; nf++) {
                int c0 = nf * 8 + tg * 2;
                if (c0     > r0) sacc[nf][0] = -1e30f;
                if (c0 + 1 > r0) sacc[nf][1] = -1e30f;
                if (c0     > r1) sacc[nf][2] = -1e30f;
                if (c0 + 1 > r1) sacc[nf][3] = -1e30f;
            }
        }

        // ---- online softmax ----
        float rm0 = -1e30f, rm1 = -1e30f;
        #pragma unroll
        for (int nf = 0; nf < 8; nf++) {
            rm0 = fmaxf(rm0, fmaxf(sacc[nf][0], sacc[nf][1]));
            rm1 = fmaxf(rm1, fmaxf(sacc[nf][2], sacc[nf][3]));
        }
        rm0 = fmaxf(rm0, __shfl_xor_sync(0xffffffffu, rm0, 1));
        rm0 = fmaxf(rm0, __shfl_xor_sync(0xffffffffu, rm0, 2));
        rm1 = fmaxf(rm1, __shfl_xor_sync(0xffffffffu, rm1, 1));
        rm1 = fmaxf(rm1, __shfl_xor_sync(0xffffffffu, rm1, 2));
        float mn0 = fmaxf(m0, rm0), mn1 = fmaxf(m1, rm1);
        float cr0 = __expf(m0 - mn0), cr1 = __expf(m1 - mn1);
        l0 *= cr0; l1 *= cr1;
        #pragma unroll
        for (int d = 0; d < 8; d++) {
            oacc[d][0] *= cr0; oacc[d][1] *= cr0;
            oacc[d][2] *= cr1; oacc[d][3] *= cr1;
        }
        m0 = mn0; m1 = mn1;

        uint32_t pf[4][4];
        #pragma unroll
        for (int sf = 0; sf < 4; sf++) {
            float e00 = __expf(sacc[2 * sf][0] - m0);
            float e01 = __expf(sacc[2 * sf][1] - m0);
            float e02 = __expf(sacc[2 * sf][2] - m1);
            float e03 = __expf(sacc[2 * sf][3] - m1);
            float e10 = __expf(sacc[2 * sf + 1][0] - m0);
            float e11 = __expf(sacc[2 * sf + 1][1] - m0);
            float e12 = __expf(sacc[2 * sf + 1][2] - m1);
            float e13 = __expf(sacc[2 * sf + 1][3] - m1);
            l0 += e00 + e01 + e10 + e11;
            l1 += e02 + e03 + e12 + e13;
            pf[sf][0] = pack_h2(e00, e01);
            pf[sf][1] = pack_h2(e02, e03);
            pf[sf][2] = pack_h2(e10, e11);
            pf[sf][3] = pack_h2(e12, e13);
        }

        // ---- O += P V ----
        #pragma unroll
        for (int sf = 0; sf < 4; sf++) {
            uint32_t vf[8][2];
            #pragma unroll
            for (int dp = 0; dp < 4; dp++)
                LDSM_X4_T(vf[dp * 2][0], vf[dp * 2][1], vf[dp * 2 + 1][0], vf[dp * 2 + 1][1],
                          vb + SMEM_SWIZZLE_128B((uint32_t)((sf * 16 + v_row) * 128 + (dp * 16 + v_col) * 2)));
            #pragma unroll
            for (int df = 0; df < 8; df++) MMA16816F16(oacc[df], pf[sf], vf[df]);
        }

        if (kt < qt) { CP_WAIT(0); __syncthreads(); }
    }

    // final: full row-sum of l, normalize, write fp16
    l0 += __shfl_xor_sync(0xffffffffu, l0, 1);
    l0 += __shfl_xor_sync(0xffffffffu, l0, 2);
    l1 += __shfl_xor_sync(0xffffffffu, l1, 1);
    l1 += __shfl_xor_sync(0xffffffffu, l1, 2);
    float i0 = 1.f / l0, i1 = 1.f / l1;
    size_t tok0 = (size_t)(b * Tt + qt * 64 + wid * 16 + gid);
    #pragma unroll
    for (int df = 0; df < 8; df++) {
        int col = h * HSZ + df * 8 + tg * 2;
        __half2 h0 = __floats2half2_rn(oacc[df][0] * i0, oacc[df][1] * i0);
        *reinterpret_cast<__half2*>(o + tok0 * Cc + col) = h0;
        __half2 h1 = __floats2half2_rn(oacc[df][2] * i1, oacc[df][3] * i1);
        *reinterpret_cast<__half2*>(o + (tok0 + 8) * Cc + col) = h1;
    }
}

// ================= host launch =================
template <typename T>
static T* sym_addr(const T* symbol) {
    void* p = nullptr;
    cudaGetSymbolAddress(&p, (const void*)symbol);
    return (T*)p;
}

extern "C" void kernel_launch(void* const* d_in, const int* in_sizes, int n_in,
                              void* d_out, int out_size) {
    const float* x   = (const float*)d_in[0];
    const float* Wq  = (const float*)d_in[1];
    const float* Wk  = (const float*)d_in[2];
    const float* Wv  = (const float*)d_in[3];
    const float* Wp  = (const float*)d_in[4];
    const float* bp  = (const float*)d_in[5];
    const float* W1  = (const float*)d_in[6];
    const float* b1  = (const float*)d_in[7];
    const float* W2  = (const float*)d_in[8];
    const float* b2  = (const float*)d_in[9];
    const float* g1  = (const float*)d_in[10];
    const float* be1 = (const float*)d_in[11];
    const float* g2  = (const float*)d_in[12];
    const float* be2 = (const float*)d_in[13];
    float* out = (float*)d_out;

    __half* p_h    = sym_addr(g_h);
    __half* p_qkvh = sym_addr(g_qkvh);
    __half* p_o    = sym_addr(g_o);
    float*  p_x1   = sym_addr(g_x1);
    __half* p_h2   = sym_addr(g_h2);
    __half* p_ff   = sym_addr(g_ff);
    __half* p_wqkvT = sym_addr(g_wqkvT);
    __half* p_wpT   = sym_addr(g_wpT);
    __half* p_w1T   = sym_addr(g_w1T);
    __half* p_w2T   = sym_addr(g_w2T);

    cudaFuncSetAttribute(mma_gemm_kernel<0,0,0,0,1>, cudaFuncAttributeMaxDynamicSharedMemorySize, GEMM_DSMEM);
    cudaFuncSetAttribute(mma_gemm_kernel<1,1,0,1,0>, cudaFuncAttributeMaxDynamicSharedMemorySize, GEMM_DSMEM);
    cudaFuncSetAttribute(mma_gemm_kernel<1,0,1,0,1>, cudaFuncAttributeMaxDynamicSharedMemorySize, GEMM_DSMEM);

    // 1. weight packing (transposed, fp16)
    pack_qkvT_kernel<<<(NQKV * Cc + 255) / 256, 256>>>(Wq, Wk, Wv);
    convT_kernel<<<(Cc * Cc + 255) / 256, 256>>>(Wp, p_wpT, Cc, Cc);
    convT_kernel<<<(Cc * FF + 255) / 256, 256>>>(W1, p_w1T, Cc, FF);
    convT_kernel<<<(FF * Cc + 255) / 256, 256>>>(W2, p_w2T, FF, Cc);

    // 2. LN1 -> fp16
    ln_kernel<<<MM, 128>>>(x, g1, be1, p_h);

    // 3. fused QKV projection -> fp16 qkv
    mma_gemm_kernel<0,0,0,0,1><<<dim3(NQKV / 128, MM / 128), 256, GEMM_DSMEM>>>(
        p_h, p_wqkvT, nullptr, nullptr, nullptr, p_qkvh, MM, NQKV, Cc);

    // 4. flash attention (tensor cores) -> o fp16
    fattn_kernel<<<dim3(Tt / 64, Hh, Bb), 128>>>(p_qkvh, p_o);

    // 5. output projection + bias + residual -> x1 fp32
    mma_gemm_kernel<1,1,0,1,0><<<dim3(Cc / 128, MM / 128), 256, GEMM_DSMEM>>>(
        p_o, p_wpT, bp, x, p_x1, nullptr, MM, Cc, Cc);

    // 6. LN2 -> fp16
    ln_kernel<<<MM, 128>>>(p_x1, g2, be2, p_h2);

    // 7. FF1 + bias + relu -> ff fp16
    mma_gemm_kernel<1,0,1,0,1><<<dim3(FF / 128, MM / 128), 256, GEMM_DSMEM>>>(
        p_h2, p_w1T, b1, nullptr, nullptr, p_ff, MM, FF, Cc);

    // 8. FF2 + bias + residual -> final output fp32
    mma_gemm_kernel<1,1,0,1,0><<<dim3(Cc / 128, MM / 128), 256, GEMM_DSMEM>>>(
        p_ff, p_w2T, b2, p_x1, out, nullptr, MM, Cc, FF);
}

// round 13
// speedup vs baseline: 2.9786x; 1.1084x over previous
#include <cuda_runtime.h>
#include <cuda_fp16.h>
#include <cstdint>

// Problem dims
#define Bb   64
#define Tt   256
#define Cc   384
#define Hh   6
#define HSZ  64
#define MM   (Bb*Tt)     // 16384 tokens
#define NQKV (3*Cc)      // 1152
#define FF   (4*Cc)      // 1536

// ================= helpers =================
__device__ __forceinline__ uint32_t smem_u32(const void* p) {
    uint32_t a;
    asm("{ .reg .u64 t; cvta.to.shared.u64 t, %1; cvt.u32.u64 %0, t; }" : "=r"(a) : "l"(p));
    return a;
}
#define SMEM_SWIZZLE_128B(off) ((off) ^ (((off) >> 3) & 0x70))

#define CP_ASYNC16(dst, src) \
    asm volatile("cp.async.cg.shared.global [%0], [%1], 16;" :: "r"(dst), "l"(src))
#define CP_COMMIT() asm volatile("cp.async.commit_group;" ::: "memory")
#define CP_WAIT(n)  asm volatile("cp.async.wait_group %0;" :: "n"(n) : "memory")

#define LDSM_X4(r0, r1, r2, r3, addr) \
    asm volatile("ldmatrix.sync.aligned.m8n8.x4.shared.b16 {%0,%1,%2,%3}, [%4];" \
        : "=r"(r0), "=r"(r1), "=r"(r2), "=r"(r3) : "r"(addr))

#define LDSM_X4_T(r0, r1, r2, r3, addr) \
    asm volatile("ldmatrix.sync.aligned.m8n8.x4.trans.shared.b16 {%0,%1,%2,%3}, [%4];" \
        : "=r"(r0), "=r"(r1), "=r"(r2), "=r"(r3) : "r"(addr))

#define MMA16816F16(d, a, b) \
    asm volatile("mma.sync.aligned.m16n8k16.row.col.f32.f16.f16.f32 " \
        "{%0,%1,%2,%3}, {%4,%5,%6,%7}, {%8,%9}, {%0,%1,%2,%3};" \
        : "+f"((d)[0]), "+f"((d)[1]), "+f"((d)[2]), "+f"((d)[3]) \
        : "r"((a)[0]), "r"((a)[1]), "r"((a)[2]), "r"((a)[3]), "r"((b)[0]), "r"((b)[1]))

__device__ __forceinline__ uint32_t pack_h2(float a, float b) {
    __half2 h = __floats2half2_rn(a, b);
    return *reinterpret_cast<uint32_t*>(&h);
}

// ================= scratch (device globals) =================
__device__ __align__(16) __half g_h   [MM*Cc];
__device__ __align__(16) __half g_qkvh[MM*NQKV];   // fp16 q|k|v
__device__ __align__(16) __half g_o   [MM*Cc];
__device__ __align__(16) float  g_x1  [MM*Cc];
__device__ __align__(16) __half g_h2  [MM*Cc];
__device__ __align__(16) __half g_ff  [MM*FF];
// weights: single fp16, transposed to [N][K]
__device__ __align__(16) __half g_wqkvT[NQKV*Cc];
__device__ __align__(16) __half g_wpT  [Cc*Cc];
__device__ __align__(16) __half g_w1T  [FF*Cc];
__device__ __align__(16) __half g_w2T  [Cc*FF];

// ================= fused weight pack (one launch) =================
#define SEG0 (NQKV*Cc)          // 442368
#define SEG1 (Cc*Cc)            // 147456
#define SEG2 (FF*Cc)            // 589824
#define SEG3 (Cc*FF)            // 589824
#define PACK_TOTAL (SEG0+SEG1+SEG2+SEG3)

__global__ void pack_all_kernel(const float* __restrict__ Wq, const float* __restrict__ Wk,
                                const float* __restrict__ Wv, const float* __restrict__ Wp,
                                const float* __restrict__ W1, const float* __restrict__ W2) {
    int idx = blockIdx.x * 256 + threadIdx.x;
    if (idx < SEG0) {
        int n = idx / Cc, k = idx % Cc;
        int which = n / Cc, hd = n % Cc;
        int h = hd / HSZ, d = hd % HSZ;
        const float* W = (which == 0) ? Wq : (which == 1) ? Wk : Wv;
        g_wqkvT[idx] = __float2half(W[(h * Cc + k) * HSZ + d]);
        return;
    }
    idx -= SEG0;
    if (idx < SEG1) {
        int n = idx / Cc, k = idx % Cc;
        g_wpT[idx] = __float2half(Wp[(size_t)k * Cc + n]);
        return;
    }
    idx -= SEG1;
    if (idx < SEG2) {
        int n = idx / Cc, k = idx % Cc;
        g_w1T[idx] = __float2half(W1[(size_t)k * FF + n]);
        return;
    }
    idx -= SEG2;
    if (idx < SEG3) {
        int n = idx / FF, k = idx % FF;
        g_w2T[idx] = __float2half(W2[(size_t)k * Cc + n]);
        return;
    }
}

// ================= LayerNorm (warp per row, no block barrier) =================
__global__ __launch_bounds__(256)
void ln_kernel(const float* __restrict__ x,
               const float* __restrict__ gamma,
               const float* __restrict__ beta,
               __half* __restrict__ y) {
    int row  = blockIdx.x * 8 + (threadIdx.x >> 5);
    int lane = threadIdx.x & 31;
    const float* xr = x + (size_t)row * Cc;
    float v[12];
    float s = 0.f, sq = 0.f;
    #pragma unroll
    for (int i = 0; i < 12; i++) {
        v[i] = xr[lane + 32 * i];
        s += v[i];
        sq += v[i] * v[i];
    }
    #pragma unroll
    for (int o = 16; o > 0; o >>= 1) {
        s  += __shfl_xor_sync(0xffffffffu, s,  o);
        sq += __shfl_xor_sync(0xffffffffu, sq, o);
    }
    float mu  = s / (float)Cc;
    float inv = rsqrtf(sq / (float)Cc - mu * mu + 1e-3f);
    size_t base = (size_t)row * Cc;
    #pragma unroll
    for (int i = 0; i < 12; i++) {
        int c = lane + 32 * i;
        y[base + c] = __float2half((v[i] - mu) * inv * gamma[c] + beta[c]);
    }
}

// ================= mma.sync fp16 GEMM, 3-stage cp.async pipeline ============
// C[M,N] = A[M,K] * B^T, A=[M][K] fp16, B=[N][K] fp16.
// CTA tile 128x128, BK=64, 3-stage pipeline, ONE __syncthreads per chunk.
// 256 threads / 8 warps, each warp 64x32.
#define BUFSZ   32768
#define GEMM_DSMEM (1024 + 3 * BUFSZ)

__device__ __forceinline__ void load_tile_async(const __half* __restrict__ src,
                                                int row0, int k0, int Ktot,
                                                uint32_t dstbase, int tid) {
    #pragma unroll
    for (int j = 0; j < 4; j++) {
        int idx = tid + j * 256;
        int r = idx >> 3, c16 = idx & 7;
        const __half* g = src + (size_t)(row0 + r) * Ktot + k0 + c16 * 8;
        uint32_t s = dstbase + SMEM_SWIZZLE_128B((uint32_t)(r * 128 + c16 * 16));
        CP_ASYNC16(s, g);
    }
}

template<int BIAS, int RES, int RELU, int F32OUT, int HOUT>
__global__ __launch_bounds__(256)
void mma_gemm_kernel(const __half* __restrict__ A,
                     const __half* __restrict__ Bw,
                     const float* __restrict__ bias, const float* __restrict__ res,
                     float* __restrict__ Cf, __half* __restrict__ Ch,
                     int M, int N, int K) {
    extern __shared__ char dsm[];
    uint32_t raw  = smem_u32(dsm);
    uint32_t base = (raw + 1023) & ~1023u;

    int tid = threadIdx.x, wid = tid >> 5, lane = tid & 31;
    int warp_m = (wid >> 2) * 64;
    int warp_n = (wid & 3) * 32;
    int m0 = blockIdx.y * 128, n0 = blockIdx.x * 128;
    int nch = K >> 6;

    float acc[4][4][4];
    #pragma unroll
    for (int a = 0; a < 4; a++)
        #pragma unroll
        for (int b = 0; b < 4; b++)
            #pragma unroll
            for (int c = 0; c < 4; c++) acc[a][b][c] = 0.f;

    // prologue: chunks 0,1 -> bufs 0,1 (separate commit groups)
    load_tile_async(A,  m0, 0, K, base + 0,     tid);
    load_tile_async(Bw, n0, 0, K, base + 16384, tid);
    CP_COMMIT();
    if (nch > 1) {
        load_tile_async(A,  m0, 64, K, base + BUFSZ + 0,     tid);
        load_tile_async(Bw, n0, 64, K, base + BUFSZ + 16384, tid);
        CP_COMMIT();
    }

    int q = lane >> 3, rin = lane & 7;
    int a_row_off = (q & 1) * 8 + rin;
    int a_col_off = (q >> 1) * 8;
    int b_row_off = (q >> 1) * 8 + rin;
    int b_col_off = (q & 1) * 8;

    for (int i = 0; i < nch; i++) {
        if (i + 1 < nch) { CP_WAIT(1); } else { CP_WAIT(0); }
        __syncthreads();   // all warps done with compute of chunk i-1; chunk i loaded

        uint32_t buf = base + (uint32_t)(i % 3) * BUFSZ;
        uint32_t sA = buf + 0, sB = buf + 16384;

        #pragma unroll
        for (int ks = 0; ks < 4; ks++) {
            uint32_t af[4][4], bw[4][2];
            #pragma unroll
            for (int mf = 0; mf < 4; mf++) {
                uint32_t off = (uint32_t)((warp_m + mf * 16 + a_row_off) * 128 +
                                          (ks * 16 + a_col_off) * 2);
                LDSM_X4(af[mf][0], af[mf][1], af[mf][2], af[mf][3],
                        sA + SMEM_SWIZZLE_128B(off));
            }
            #pragma unroll
            for (int nf2 = 0; nf2 < 2; nf2++) {
                uint32_t off = (uint32_t)((warp_n + nf2 * 16 + b_row_off) * 128 +
                                          (ks * 16 + b_col_off) * 2);
                LDSM_X4(bw[nf2 * 2][0], bw[nf2 * 2][1], bw[nf2 * 2 + 1][0], bw[nf2 * 2 + 1][1],
                        sB + SMEM_SWIZZLE_128B(off));
            }
            #pragma unroll
            for (int mf = 0; mf < 4; mf++)
                #pragma unroll
                for (int nf = 0; nf < 4; nf++) MMA16816F16(acc[mf][nf], af[mf], bw[nf]);
        }

        // prefetch chunk i+2 into buf (i+2)%3 (safe: all warps finished chunk i-1)
        if (i + 2 < nch) {
            uint32_t nb = base + (uint32_t)((i + 2) % 3) * BUFSZ;
            int k0 = (i + 2) << 6;
            load_tile_async(A,  m0, k0, K, nb + 0,     tid);
            load_tile_async(Bw, n0, k0, K, nb + 16384, tid);
            CP_COMMIT();
        }
    }

    int tr = lane >> 2, tc = (lane & 3) * 2;
    #pragma unroll
    for (int mf = 0; mf < 4; mf++) {
        #pragma unroll
        for (int nf = 0; nf < 4; nf++) {
            int col = n0 + warp_n + nf * 8 + tc;
            #pragma unroll
            for (int half = 0; half < 2; half++) {
                int row = m0 + warp_m + mf * 16 + tr + half * 8;
                float v0 = acc[mf][nf][half * 2 + 0];
                float v1 = acc[mf][nf][half * 2 + 1];
                if (BIAS) { v0 += bias[col]; v1 += bias[col + 1]; }
                size_t oidx = (size_t)row * N + col;
                if (RES)  { v0 += res[oidx]; v1 += res[oidx + 1]; }
                if (RELU) { v0 = fmaxf(v0, 0.f); v1 = fmaxf(v1, 0.f); }
                if (F32OUT) { Cf[oidx] = v0; Cf[oidx + 1] = v1; }
                if (HOUT) {
                    Ch[oidx]     = __float2half(v0);
                    Ch[oidx + 1] = __float2half(v1);
                }
            }
        }
    }
}

// ================= flash attention (mma.sync fp16) =================
__device__ __forceinline__ void fattn_load_kv(const __half* __restrict__ qkv,
                                              int b, int h, int kt,
                                              uint32_t kbase, uint32_t vbase, int tid) {
    #pragma unroll
    for (int j = 0; j < 4; j++) {
        int idx = tid + j * 128;
        int r = idx >> 3, c = idx & 7;
        const __half* ks = qkv + (size_t)(b * Tt + kt * 64 + r) * NQKV + Cc + h * HSZ + c * 8;
        CP_ASYNC16(kbase + SMEM_SWIZZLE_128B((uint32_t)(r * 128 + c * 16)), ks);
    }
    #pragma unroll
    for (int j = 0; j < 4; j++) {
        int idx = tid + j * 128;
        int r = idx >> 3, c = idx & 7;
        const __half* vs = qkv + (size_t)(b * Tt + kt * 64 + r) * NQKV + 2 * Cc + h * HSZ + c * 8;
        CP_ASYNC16(vbase + SMEM_SWIZZLE_128B((uint32_t)(r * 128 + c * 16)), vs);
    }
}

__global__ __launch_bounds__(128)
void fattn_kernel(const __half* __restrict__ qkv, __half* __restrict__ o) {
    __shared__ __align__(1024) __half smem[5 * 4096];
    int tid = threadIdx.x, wid = tid >> 5, lane = tid & 31;
    int b = blockIdx.z, h = blockIdx.y, qt = blockIdx.x;
    uint32_t sbase = smem_u32(smem);
    uint32_t qb = sbase;
    uint32_t kb0 = sbase + 8192,  kb1 = sbase + 16384;
    uint32_t vb0 = sbase + 24576, vb1 = sbase + 32768;

    #pragma unroll
    for (int j = 0; j < 4; j++) {
        int idx = tid + j * 128;
        int r = idx >> 3, c = idx & 7;
        const __half* src = qkv + (size_t)(b * Tt + qt * 64 + r) * NQKV + h * HSZ + c * 8;
        CP_ASYNC16(qb + SMEM_SWIZZLE_128B((uint32_t)(r * 128 + c * 16)), src);
    }
    fattn_load_kv(qkv, b, h, 0, kb0, vb0, tid);
    CP_COMMIT();
    CP_WAIT(0);
    __syncthreads();

    int q8 = lane >> 3, rin = lane & 7;
    int a_row = (q8 & 1) * 8 + rin, a_col = (q8 >> 1) * 8;
    int b_row = (q8 >> 1) * 8 + rin, b_col = (q8 & 1) * 8;
    int vm = lane >> 3;
    int v_row = (vm & 1) * 8 + (lane & 7);
    int v_col = (vm >> 1) * 8;
    int tg = lane & 3, gid = lane >> 2;

    uint32_t qf[4][4];
    #pragma unroll
    for (int kc = 0; kc < 4; kc++)
        LDSM_X4(qf[kc][0], qf[kc][1], qf[kc][2], qf[kc][3],
                qb + SMEM_SWIZZLE_128B((uint32_t)((wid * 16 + a_row) * 128 + (kc * 16 + a_col) * 2)));

    float oacc[8][4];
    #pragma unroll
    for (int d = 0; d < 8; d++)
        #pragma unroll
        for (int e = 0; e < 4; e++) oacc[d][e] = 0.f;
    float m0 = -1e30f, m1 = -1e30f, l0 = 0.f, l1 = 0.f;

    for (int kt = 0; kt <= qt; kt++) {
        uint32_t kb = (kt & 1) ? kb1 : kb0;
        uint32_t vb = (kt & 1) ? vb1 : vb0;
        if (kt < qt) {
            fattn_load_kv(qkv, b, h, kt + 1, (kt & 1) ? kb0 : kb1, (kt & 1) ? vb0 : vb1, tid);
            CP_COMMIT();
        }

        float sacc[8][4];
        #pragma unroll
        for (int n = 0; n < 8; n++)
            #pragma unroll
            for (int e = 0; e < 4; e++) sacc[n][e] = 0.f;
        #pragma unroll
        for (int kc = 0; kc < 4; kc++) {
            uint32_t bw[8][2];
            #pragma unroll
            for (int nf2 = 0; nf2 < 4; nf2++)
                LDSM_X4(bw[nf2 * 2][0], bw[nf2 * 2][1], bw[nf2 * 2 + 1][0], bw[nf2 * 2 + 1][1],
                        kb + SMEM_SWIZZLE_128B((uint32_t)((nf2 * 16 + b_row) * 128 + (kc * 16 + b_col) * 2)));
            #pragma unroll
            for (int nf = 0; nf < 8; nf++) MMA16816F16(sacc[nf], qf[kc], bw[nf]);
        }

        #pragma unroll
        for (int nf = 0; nf < 8; nf++)
            #pragma unroll
            for (int e = 0; e < 4; e++) sacc[nf][e] *= 0.125f;
        if (kt == qt) {
            int r0 = wid * 16 + gid, r1 = r0 + 8;
            #pragma unroll
            for (int nf = 0; nf < 8; nf++) {
                int c0 = nf * 8 + tg * 2;
                if (c0     > r0) sacc[nf][0] = -1e30f;
                if (c0 + 1 > r0) sacc[nf][1] = -1e30f;
                if (c0     > r1) sacc[nf][2] = -1e30f;
                if (c0 + 1 > r1) sacc[nf][3] = -1e30f;
            }
        }

        float rm0 = -1e30f, rm1 = -1e30f;
        #pragma unroll
        for (int nf = 0; nf < 8; nf++) {
            rm0 = fmaxf(rm0, fmaxf(sacc[nf][0], sacc[nf][1]));
            rm1 = fmaxf(rm1, fmaxf(sacc[nf][2], sacc[nf][3]));
        }
        rm0 = fmaxf(rm0, __shfl_xor_sync(0xffffffffu, rm0, 1));
        rm0 = fmaxf(rm0, __shfl_xor_sync(0xffffffffu, rm0, 2));
        rm1 = fmaxf(rm1, __shfl_xor_sync(0xffffffffu, rm1, 1));
        rm1 = fmaxf(rm1, __shfl_xor_sync(0xffffffffu, rm1, 2));
        float mn0 = fmaxf(m0, rm0), mn1 = fmaxf(m1, rm1);
        float cr0 = __expf(m0 - mn0), cr1 = __expf(m1 - mn1);
        l0 *= cr0; l1 *= cr1;
        #pragma unroll
        for (int d = 0; d < 8; d++) {
            oacc[d][0] *= cr0; oacc[d][1] *= cr0;
            oacc[d][2] *= cr1; oacc[d][3] *= cr1;
        }
        m0 = mn0; m1 = mn1;

        uint32_t pf[4][4];
        #pragma unroll
        for (int sf = 0; sf < 4; sf++) {
            float e00 = __expf(sacc[2 * sf][0] - m0);
            float e01 = __expf(sacc[2 * sf][1] - m0);
            float e02 = __expf(sacc[2 * sf][2] - m1);
            float e03 = __expf(sacc[2 * sf][3] - m1);
            float e10 = __expf(sacc[2 * sf + 1][0] - m0);
            float e11 = __expf(sacc[2 * sf + 1][1] - m0);
            float e12 = __expf(sacc[2 * sf + 1][2] - m1);
            float e13 = __expf(sacc[2 * sf + 1][3] - m1);
            l0 += e00 + e01 + e10 + e11;
            l1 += e02 + e03 + e12 + e13;
            pf[sf][0] = pack_h2(e00, e01);
            pf[sf][1] = pack_h2(e02, e03);
            pf[sf][2] = pack_h2(e10, e11);
            pf[sf][3] = pack_h2(e12, e13);
        }

        #pragma unroll
        for (int sf = 0; sf < 4; sf++) {
            uint32_t vf[8][2];
            #pragma unroll
            for (int dp = 0; dp < 4; dp++)
                LDSM_X4_T(vf[dp * 2][0], vf[dp * 2][1], vf[dp * 2 + 1][0], vf[dp * 2 + 1][1],
                          vb + SMEM_SWIZZLE_128B((uint32_t)((sf * 16 + v_row) * 128 + (dp * 16 + v_col) * 2)));
            #pragma unroll
            for (int df = 0; df < 8; df++) MMA16816F16(oacc[df], pf[sf], vf[df]);
        }

        if (kt < qt) { CP_WAIT(0); __syncthreads(); }
    }

    l0 += __shfl_xor_sync(0xffffffffu, l0, 1);
    l0 += __shfl_xor_sync(0xffffffffu, l0, 2);
    l1 += __shfl_xor_sync(0xffffffffu, l1, 1);
    l1 += __shfl_xor_sync(0xffffffffu, l1, 2);
    float i0 = 1.f / l0, i1 = 1.f / l1;
    size_t tok0 = (size_t)(b * Tt + qt * 64 + wid * 16 + gid);
    #pragma unroll
    for (int df = 0; df < 8; df++) {
        int col = h * HSZ + df * 8 + tg * 2;
        __half2 h0 = __floats2half2_rn(oacc[df][0] * i0, oacc[df][1] * i0);
        *reinterpret_cast<__half2*>(o + tok0 * Cc + col) = h0;
        __half2 h1 = __floats2half2_rn(oacc[df][2] * i1, oacc[df][3] * i1);
        *reinterpret_cast<__half2*>(o + (tok0 + 8) * Cc + col) = h1;
    }
}

// ================= host launch =================
template <typename T>
static T* sym_addr(const T* symbol) {
    void* p = nullptr;
    cudaGetSymbolAddress(&p, (const void*)symbol);
    return (T*)p;
}

extern "C" void kernel_launch(void* const* d_in, const int* in_sizes, int n_in,
                              void* d_out, int out_size) {
    const float* x   = (const float*)d_in[0];
    const float* Wq  = (const float*)d_in[1];
    const float* Wk  = (const float*)d_in[2];
    const float* Wv  = (const float*)d_in[3];
    const float* Wp  = (const float*)d_in[4];
    const float* bp  = (const float*)d_in[5];
    const float* W1  = (const float*)d_in[6];
    const float* b1  = (const float*)d_in[7];
    const float* W2  = (const float*)d_in[8];
    const float* b2  = (const float*)d_in[9];
    const float* g1  = (const float*)d_in[10];
    const float* be1 = (const float*)d_in[11];
    const float* g2  = (const float*)d_in[12];
    const float* be2 = (const float*)d_in[13];
    float* out = (float*)d_out;

    __half* p_h    = sym_addr(g_h);
    __half* p_qkvh = sym_addr(g_qkvh);
    __half* p_o    = sym_addr(g_o);
    float*  p_x1   = sym_addr(g_x1);
    __half* p_h2   = sym_addr(g_h2);
    __half* p_ff   = sym_addr(g_ff);
    __half* p_wqkvT = sym_addr(g_wqkvT);
    __half* p_wpT   = sym_addr(g_wpT);
    __half* p_w1T   = sym_addr(g_w1T);
    __half* p_w2T   = sym_addr(g_w2T);
    (void)p_wqkvT; (void)p_wpT; (void)p_w1T; (void)p_w2T;

    cudaFuncSetAttribute(mma_gemm_kernel<0,0,0,0,1>, cudaFuncAttributeMaxDynamicSharedMemorySize, GEMM_DSMEM);
    cudaFuncSetAttribute(mma_gemm_kernel<1,1,0,1,0>, cudaFuncAttributeMaxDynamicSharedMemorySize, GEMM_DSMEM);
    cudaFuncSetAttribute(mma_gemm_kernel<1,0,1,0,1>, cudaFuncAttributeMaxDynamicSharedMemorySize, GEMM_DSMEM);

    // 1. fused weight packing (one launch)
    pack_all_kernel<<<(PACK_TOTAL + 255) / 256, 256>>>(Wq, Wk, Wv, Wp, W1, W2);

    // 2. LN1 -> fp16
    ln_kernel<<<MM / 8, 256>>>(x, g1, be1, p_h);

    // 3. fused QKV projection -> fp16 qkv
    mma_gemm_kernel<0,0,0,0,1><<<dim3(NQKV / 128, MM / 128), 256, GEMM_DSMEM>>>(
        p_h, p_wqkvT, nullptr, nullptr, nullptr, p_qkvh, MM, NQKV, Cc);

    // 4. flash attention (tensor cores) -> o fp16
    fattn_kernel<<<dim3(Tt / 64, Hh, Bb), 128>>>(p_qkvh, p_o);

    // 5. output projection + bias + residual -> x1 fp32
    mma_gemm_kernel<1,1,0,1,0><<<dim3(Cc / 128, MM / 128), 256, GEMM_DSMEM>>>(
        p_o, p_wpT, bp, x, p_x1, nullptr, MM, Cc, Cc);

    // 6. LN2 -> fp16
    ln_kernel<<<MM / 8, 256>>>(p_x1, g2, be2, p_h2);

    // 7. FF1 + bias + relu -> ff fp16
    mma_gemm_kernel<1,0,1,0,1><<<dim3(FF / 128, MM / 128), 256, GEMM_DSMEM>>>(
        p_h2, p_w1T, b1, nullptr, nullptr, p_ff, MM, FF, Cc);

    // 8. FF2 + bias + residual -> final output fp32
    mma_gemm_kernel<1,1,0,1,0><<<dim3(Cc / 128, MM / 128), 256, GEMM_DSMEM>>>(
        p_ff, p_w2T, b2, p_x1, out, nullptr, MM, Cc, FF);
}